// round 11
// baseline (speedup 1.0000x reference)
#include <cuda_runtime.h>
#include <cuda_fp16.h>
#include <mma.h>
#include <math.h>
#include <cstdint>

using namespace nvcuda;

// Problem dims
#define BATCH 16
#define SEQ   512
#define EMB   1024
#define FF    4096
#define HEADS 16
#define HDIM  64
#define ROWS  (BATCH*SEQ)        // 8192
#define BH    (BATCH*HEADS)      // 256

// ---------------- scratch (device globals; no allocation allowed) ----------------
__device__ __half g_wH[12*1024*1024];          // wq,wk,wv,wo (1M ea), w1 (4M), w2 (4M)
__device__ __half g_xh[ROWS*EMB];              // LN out (half)
__device__ __half g_qh[ROWS*EMB];
__device__ __half g_kh[ROWS*EMB];
__device__ __half g_vh[ROWS*EMB];
__device__ __half g_ah[ROWS*EMB];              // attention out (half)
__device__ __half g_hh[ROWS*FF];               // MLP hidden (half)
__device__ float  g_x[ROWS*EMB];               // residual stream (fp32)

// ---------------- helpers ----------------
__device__ __forceinline__ void cp_async16(void* smem_dst, const void* gsrc) {
    unsigned s = (unsigned)__cvta_generic_to_shared(smem_dst);
    asm volatile("cp.async.cg.shared.global [%0], [%1], 16;\n" :: "r"(s), "l"(gsrc));
}
__device__ __forceinline__ void cp_commit() {
    asm volatile("cp.async.commit_group;\n");
}
__device__ __forceinline__ float gelu_exact(float y) {
    return 0.5f * y * (1.0f + erff(y * 0.70710678118654752f));
}
__device__ __forceinline__ void st_half4(__half* p, float4 v) {
    __half2* p2 = reinterpret_cast<__half2*>(p);
    p2[0] = __floats2half2_rn(v.x, v.y);
    p2[1] = __floats2half2_rn(v.z, v.w);
}

// ---------------- weight conversion: half(in[i]) ----------------
__global__ void cvt_half_kernel(const float* __restrict__ in, __half* __restrict__ out) {
    size_t i = (size_t)blockIdx.x * blockDim.x + threadIdx.x;
    float4 v = reinterpret_cast<const float4*>(in)[i];
    st_half4(out + i * 4, v);
}

// ---------------- LayerNorm: fp32 in, half out ----------------
__global__ void ln_kernel(const float* __restrict__ in, const float* __restrict__ gam,
                          const float* __restrict__ bet, __half* __restrict__ out) {
    int row = blockIdx.x;
    int t = threadIdx.x;
    const float4* inr = reinterpret_cast<const float4*>(in + (size_t)row * EMB);
    float4 x = inr[t];
    float s  = x.x + x.y + x.z + x.w;
    float sq = x.x*x.x + x.y*x.y + x.z*x.z + x.w*x.w;
    #pragma unroll
    for (int o = 16; o > 0; o >>= 1) {
        s  += __shfl_xor_sync(0xffffffffu, s,  o);
        sq += __shfl_xor_sync(0xffffffffu, sq, o);
    }
    __shared__ float sa[8], sb[8];
    int w = t >> 5, l = t & 31;
    if (l == 0) { sa[w] = s; sb[w] = sq; }
    __syncthreads();
    s = 0.f; sq = 0.f;
    #pragma unroll
    for (int i = 0; i < 8; i++) { s += sa[i]; sq += sb[i]; }
    float mean = s * (1.0f / EMB);
    float var  = sq * (1.0f / EMB) - mean * mean;
    float rstd = rsqrtf(var + 1e-5f);
    float4 g4 = reinterpret_cast<const float4*>(gam)[t];
    float4 b4 = reinterpret_cast<const float4*>(bet)[t];
    float4 o4;
    o4.x = (x.x - mean) * rstd * g4.x + b4.x;
    o4.y = (x.y - mean) * rstd * g4.y + b4.y;
    o4.z = (x.z - mean) * rstd * g4.z + b4.z;
    o4.w = (x.w - mean) * rstd * g4.w + b4.w;
    st_half4(out + (size_t)row * EMB + t * 4, o4);
}

// ---------------- FP16 GEMM, double-buffered cp.async, BK=64, fused epilogue ----------
#define ALD 72     // halves per A row (64+8)
#define BLD 136    // halves per B row (128+8)
#define STAGE_B (128*ALD*2 + 64*BLD*2)            // 35840 bytes
#define GEMM_SMEM 71680                           // max(2*STAGE_B, 128*132*4)

template<int EPI>
__global__ __launch_bounds__(256, 2)
void gemm_h(const __half* __restrict__ A, const __half* __restrict__ B,
            const float* __restrict__ bias, const float* __restrict__ res,
            void* __restrict__ Cout, int M, int N, int K) {
    extern __shared__ char smraw[];
    __half* As[2] = { (__half*)smraw, (__half*)(smraw + STAGE_B) };
    __half* Bs[2] = { (__half*)(smraw + 128*ALD*2), (__half*)(smraw + STAGE_B + 128*ALD*2) };
    float* Cs = (float*)smraw;   // epilogue alias [128][132]

    const int m0 = blockIdx.y * 128;
    const int n0 = blockIdx.x * 128;
    const int tid = threadIdx.x;
    const int warp = tid >> 5;
    const int wm = warp >> 2;      // 0..1
    const int wn = warp & 3;       // 0..3

    wmma::fragment<wmma::accumulator, 16, 16, 16, float> acc[4][2];
    #pragma unroll
    for (int i = 0; i < 4; i++)
        #pragma unroll
        for (int j = 0; j < 2; j++)
            wmma::fill_fragment(acc[i][j], 0.0f);

    auto load_stage = [&](int st, int k0) {
        #pragma unroll
        for (int p = 0; p < 4; p++) {              // A: 128 rows x 8 chunks (8 halves)
            int idx = tid + p * 256;
            int r = idx >> 3, c = (idx & 7) << 3;
            cp_async16(As[st] + r * ALD + c, A + (size_t)(m0 + r) * K + k0 + c);
        }
        #pragma unroll
        for (int p = 0; p < 4; p++) {              // B: 64 rows x 16 chunks
            int idx = tid + p * 256;
            int r = idx >> 4, c = (idx & 15) << 3;
            cp_async16(Bs[st] + r * BLD + c, B + (size_t)(k0 + r) * N + n0 + c);
        }
        cp_commit();
    };

    const int NT = K >> 6;
    load_stage(0, 0);

    for (int kt = 0; kt < NT; kt++) {
        if (kt + 1 < NT) {
            load_stage((kt + 1) & 1, (kt + 1) << 6);
            asm volatile("cp.async.wait_group 1;\n");
        } else {
            asm volatile("cp.async.wait_group 0;\n");
        }
        __syncthreads();
        const __half* as = As[kt & 1];
        const __half* bs = Bs[kt & 1];
        #pragma unroll
        for (int ks = 0; ks < 4; ks++) {
            wmma::fragment<wmma::matrix_a, 16, 16, 16, __half, wmma::row_major> af[4];
            wmma::fragment<wmma::matrix_b, 16, 16, 16, __half, wmma::row_major> bf[2];
            #pragma unroll
            for (int i = 0; i < 4; i++)
                wmma::load_matrix_sync(af[i], as + (wm * 64 + i * 16) * ALD + ks * 16, ALD);
            #pragma unroll
            for (int j = 0; j < 2; j++)
                wmma::load_matrix_sync(bf[j], bs + (ks * 16) * BLD + wn * 32 + j * 16, BLD);
            #pragma unroll
            for (int i = 0; i < 4; i++)
                #pragma unroll
                for (int j = 0; j < 2; j++)
                    wmma::mma_sync(acc[i][j], af[i], bf[j], acc[i][j]);
        }
        __syncthreads();
    }

    // epilogue via smem
    #pragma unroll
    for (int i = 0; i < 4; i++)
        #pragma unroll
        for (int j = 0; j < 2; j++)
            wmma::store_matrix_sync(Cs + (wm * 64 + i * 16) * 132 + wn * 32 + j * 16,
                                    acc[i][j], 132, wmma::mem_row_major);
    __syncthreads();

    #pragma unroll
    for (int p = 0; p < 16; p++) {
        int idx = tid + p * 256;              // 128 rows x 32 float4
        int r = idx >> 5, c = (idx & 31) << 2;
        float4 v = *reinterpret_cast<const float4*>(Cs + r * 132 + c);
        float4 b = *reinterpret_cast<const float4*>(bias + n0 + c);
        v.x += b.x; v.y += b.y; v.z += b.z; v.w += b.w;
        if (EPI == 1) {
            v.x = gelu_exact(v.x); v.y = gelu_exact(v.y);
            v.z = gelu_exact(v.z); v.w = gelu_exact(v.w);
        }
        if (EPI == 2) {
            float4 rr = *reinterpret_cast<const float4*>(res + (size_t)(m0 + r) * N + n0 + c);
            v.x += rr.x; v.y += rr.y; v.z += rr.z; v.w += rr.w;
            *reinterpret_cast<float4*>((float*)Cout + (size_t)(m0 + r) * N + n0 + c) = v;
        } else {
            st_half4((__half*)Cout + (size_t)(m0 + r) * N + n0 + c, v);
        }
    }
}

// ---------------- fused attention: per block = 32 q-rows of one (b,h) ----------------
// S(32x512) fp32 in smem (exact softmax), P half aliased in place, K/V streamed
// in 64-row chunks (double-buffered cp.async). 256 threads, 8 warps as 2x4:
// each warp owns one 16x16 output tile of the 32x64 S-chunk / O tile.
#define SS_LDF 520                            // floats per S row
#define FL_QS_OFF  66560                      // 32*520*4
#define FL_KV_OFF  71168                      // + 32*72*2
#define FL_KV_STG  9216                       // 64*72*2
#define FLASH_SMEM 89600                      // + 2*9216

__global__ __launch_bounds__(256, 2)
void flash_h(const __half* __restrict__ q, const __half* __restrict__ k,
             const __half* __restrict__ v, __half* __restrict__ o) {
    extern __shared__ char sm[];
    float*  Ss = (float*)sm;                         // [32][520]
    __half* Ph = (__half*)sm;                        // alias, row stride 1040 halves
    __half* Qs = (__half*)(sm + FL_QS_OFF);          // [32][72]
    __half* KV[2] = { (__half*)(sm + FL_KV_OFF),
                      (__half*)(sm + FL_KV_OFF + FL_KV_STG) };

    const int bh = blockIdx.y;
    const int b = bh >> 4, h = bh & 15;
    const int q0 = blockIdx.x * 32;
    const int tid = threadIdx.x;
    const int warp = tid >> 5;
    const int wm = warp >> 2;      // 0..1
    const int wn = warp & 3;       // 0..3

    // load Q tile (plain loads; own-thread store->sync ordering suffices)
    {
        int r = tid >> 3, c = (tid & 7) << 3;
        *reinterpret_cast<float4*>(Qs + r * 72 + c) =
            *reinterpret_cast<const float4*>(q + (size_t)(b * SEQ + q0 + r) * EMB + h * HDIM + c);
    }

    const __half* kbase = k + (size_t)b * SEQ * EMB + h * HDIM;
    const __half* vbase = v + (size_t)b * SEQ * EMB + h * HDIM;

    auto load_kv = [&](const __half* base, int chunk, int st) {
        #pragma unroll
        for (int p = 0; p < 2; p++) {              // 64 rows x 8 chunks of 8 halves
            int idx = tid + p * 256;
            int r = idx >> 3, c = (idx & 7) << 3;
            cp_async16(KV[st] + r * 72 + c, base + (size_t)(chunk * 64 + r) * EMB + c);
        }
        cp_commit();
    };

    load_kv(kbase, 0, 0);
    load_kv(kbase, 1, 1);

    // ---- phase 1: S = Q K^T * 1/8 ----
    for (int kc = 0; kc < 8; kc++) {
        if (kc < 7) asm volatile("cp.async.wait_group 1;\n");
        else        asm volatile("cp.async.wait_group 0;\n");
        __syncthreads();
        const __half* Ks = KV[kc & 1];
        wmma::fragment<wmma::accumulator, 16, 16, 16, float> sfrag;
        wmma::fill_fragment(sfrag, 0.0f);
        #pragma unroll
        for (int ks = 0; ks < 4; ks++) {
            wmma::fragment<wmma::matrix_a, 16, 16, 16, __half, wmma::row_major> af;
            wmma::fragment<wmma::matrix_b, 16, 16, 16, __half, wmma::col_major> bf;
            wmma::load_matrix_sync(af, Qs + (wm * 16) * 72 + ks * 16, 72);
            wmma::load_matrix_sync(bf, Ks + (wn * 16) * 72 + ks * 16, 72);
            wmma::mma_sync(sfrag, af, bf, sfrag);
        }
        #pragma unroll
        for (int e = 0; e < sfrag.num_elements; e++) sfrag.x[e] *= 0.125f;
        wmma::store_matrix_sync(Ss + (wm * 16) * SS_LDF + kc * 64 + wn * 16,
                                sfrag, SS_LDF, wmma::mem_row_major);
        __syncthreads();
        if (kc + 2 < 8) load_kv(kbase, kc + 2, kc & 1);
    }

    // start streaming V while softmax runs (both KV bufs free after phase-1 syncs)
    load_kv(vbase, 0, 0);
    load_kv(vbase, 1, 1);

    // ---- phase 2: exact softmax, in place, P as half ----
    {
        int r = tid >> 3;
        int c0 = (tid & 7) << 6;         // 64 cols per thread
        float sv[64];
        float mx = -1e30f;
        #pragma unroll
        for (int j = 0; j < 64; j++) { sv[j] = Ss[r * SS_LDF + c0 + j]; mx = fmaxf(mx, sv[j]); }
        #pragma unroll
        for (int d = 1; d < 8; d <<= 1) mx = fmaxf(mx, __shfl_xor_sync(0xffffffffu, mx, d));
        float sum = 0.f;
        #pragma unroll
        for (int j = 0; j < 64; j++) { sv[j] = __expf(sv[j] - mx); sum += sv[j]; }
        #pragma unroll
        for (int d = 1; d < 8; d <<= 1) sum += __shfl_xor_sync(0xffffffffu, sum, d);
        float inv = 1.0f / sum;
        __syncthreads();                 // all S reads complete before half overwrite
        __half2* prow = reinterpret_cast<__half2*>(Ph + r * 1040 + c0);
        #pragma unroll
        for (int j = 0; j < 64; j += 2)
            prow[j >> 1] = __floats2half2_rn(sv[j] * inv, sv[j + 1] * inv);
    }
    __syncthreads();

    // ---- phase 3: O = P V ----
    wmma::fragment<wmma::accumulator, 16, 16, 16, float> ofrag;
    wmma::fill_fragment(ofrag, 0.0f);
    for (int kc = 0; kc < 8; kc++) {
        if (kc < 7) asm volatile("cp.async.wait_group 1;\n");
        else        asm volatile("cp.async.wait_group 0;\n");
        __syncthreads();
        const __half* Vs = KV[kc & 1];
        #pragma unroll
        for (int ks = 0; ks < 4; ks++) {
            wmma::fragment<wmma::matrix_a, 16, 16, 16, __half, wmma::row_major> af;
            wmma::fragment<wmma::matrix_b, 16, 16, 16, __half, wmma::row_major> bf;
            wmma::load_matrix_sync(af, Ph + (wm * 16) * 1040 + kc * 64 + ks * 16, 1040);
            wmma::load_matrix_sync(bf, Vs + (ks * 16) * 72 + wn * 16, 72);
            wmma::mma_sync(ofrag, af, bf, ofrag);
        }
        __syncthreads();
        if (kc + 2 < 8) load_kv(vbase, kc + 2, kc & 1);
    }

    // stage O via smem (reuse Ss as float [32][72]), convert to half, write
    wmma::store_matrix_sync((float*)sm + (wm * 16) * 72 + wn * 16, ofrag, 72,
                            wmma::mem_row_major);
    __syncthreads();
    {
        int r = tid >> 3, c = (tid & 7) << 3;
        const float* Cs = (const float*)sm;
        float4 v0 = *reinterpret_cast<const float4*>(Cs + r * 72 + c);
        float4 v1 = *reinterpret_cast<const float4*>(Cs + r * 72 + c + 4);
        __half* dst = o + (size_t)(b * SEQ + q0 + r) * EMB + h * HDIM + c;
        st_half4(dst, v0);
        st_half4(dst + 4, v1);
    }
}

// ---------------- driver ----------------
extern "C" void kernel_launch(void* const* d_in, const int* in_sizes, int n_in,
                              void* d_out, int out_size) {
    const float* input = (const float*)d_in[0];
    const float* ln1_g = (const float*)d_in[1];
    const float* ln1_b = (const float*)d_in[2];
    const float* wq    = (const float*)d_in[3];
    const float* bq    = (const float*)d_in[4];
    const float* wk    = (const float*)d_in[5];
    const float* bk    = (const float*)d_in[6];
    const float* wv    = (const float*)d_in[7];
    const float* bv    = (const float*)d_in[8];
    const float* wo    = (const float*)d_in[9];
    const float* bo    = (const float*)d_in[10];
    const float* ln2_g = (const float*)d_in[11];
    const float* ln2_b = (const float*)d_in[12];
    const float* w1    = (const float*)d_in[13];
    const float* b1    = (const float*)d_in[14];
    const float* w2    = (const float*)d_in[15];
    const float* b2    = (const float*)d_in[16];
    float* out = (float*)d_out;

    __half *wH, *xh, *qh, *kh, *vh, *ah, *hh;
    float *x;
    cudaGetSymbolAddress((void**)&wH, g_wH);
    cudaGetSymbolAddress((void**)&xh, g_xh);
    cudaGetSymbolAddress((void**)&qh, g_qh);
    cudaGetSymbolAddress((void**)&kh, g_kh);
    cudaGetSymbolAddress((void**)&vh, g_vh);
    cudaGetSymbolAddress((void**)&ah, g_ah);
    cudaGetSymbolAddress((void**)&hh, g_hh);
    cudaGetSymbolAddress((void**)&x,  g_x);

    __half* wqH = wH;                       // [1024,1024]
    __half* wkH = wH + 1*1024*1024;
    __half* wvH = wH + 2*1024*1024;
    __half* woH = wH + 3*1024*1024;
    __half* w1H = wH + 4*1024*1024;         // [1024,4096]
    __half* w2H = wH + 8*1024*1024;         // [4096,1024]

    cudaFuncSetAttribute(gemm_h<0>, cudaFuncAttributeMaxDynamicSharedMemorySize, GEMM_SMEM);
    cudaFuncSetAttribute(gemm_h<1>, cudaFuncAttributeMaxDynamicSharedMemorySize, GEMM_SMEM);
    cudaFuncSetAttribute(gemm_h<2>, cudaFuncAttributeMaxDynamicSharedMemorySize, GEMM_SMEM);
    cudaFuncSetAttribute(flash_h,   cudaFuncAttributeMaxDynamicSharedMemorySize, FLASH_SMEM);

    // 0) weights -> half (one pass each)
    cvt_half_kernel<<<1024, 256>>>(wq, wqH);
    cvt_half_kernel<<<1024, 256>>>(wk, wkH);
    cvt_half_kernel<<<1024, 256>>>(wv, wvH);
    cvt_half_kernel<<<1024, 256>>>(wo, woH);
    cvt_half_kernel<<<4096, 256>>>(w1, w1H);
    cvt_half_kernel<<<4096, 256>>>(w2, w2H);

    dim3 gemmE(EMB / 128, ROWS / 128);    // (8, 64)
    dim3 gemmF(FF / 128, ROWS / 128);     // (32, 64)

    // 1) LN1 -> half
    ln_kernel<<<ROWS, 256>>>(input, ln1_g, ln1_b, xh);
    // 2) QKV projections, fused bias, half outputs
    gemm_h<0><<<gemmE, 256, GEMM_SMEM>>>(xh, wqH, bq, nullptr, qh, ROWS, EMB, EMB);
    gemm_h<0><<<gemmE, 256, GEMM_SMEM>>>(xh, wkH, bk, nullptr, kh, ROWS, EMB, EMB);
    gemm_h<0><<<gemmE, 256, GEMM_SMEM>>>(xh, wvH, bv, nullptr, vh, ROWS, EMB, EMB);
    // 3) fused attention (scores + softmax + AV)
    flash_h<<<dim3(SEQ / 32, BH), 256, FLASH_SMEM>>>(qh, kh, vh, ah);
    // 4) output projection + bias + residual (fp32 out)
    gemm_h<2><<<gemmE, 256, GEMM_SMEM>>>(ah, woH, bo, input, x, ROWS, EMB, EMB);
    // 5) LN2 -> half
    ln_kernel<<<ROWS, 256>>>(x, ln2_g, ln2_b, xh);
    // 6) MLP up + bias + GELU -> half
    gemm_h<1><<<gemmF, 256, GEMM_SMEM>>>(xh, w1H, b1, nullptr, hh, ROWS, FF, EMB);
    // 7) MLP down + bias + residual -> out (fp32)
    gemm_h<2><<<gemmE, 256, GEMM_SMEM>>>(hh, w2H, b2, x, out, ROWS, EMB, FF);
}

// round 12
// speedup vs baseline: 1.0654x; 1.0654x over previous
#include <cuda_runtime.h>
#include <cuda_fp16.h>
#include <mma.h>
#include <math.h>
#include <cstdint>

using namespace nvcuda;

// Problem dims
#define BATCH 16
#define SEQ   512
#define EMB   1024
#define FF    4096
#define HEADS 16
#define HDIM  64
#define ROWS  (BATCH*SEQ)        // 8192
#define BH    (BATCH*HEADS)      // 256
#define QKV_STR 3072             // packed q|k|v row stride

// ---------------- scratch (device globals; no allocation allowed) ----------------
__device__ __half g_wH[12*1024*1024];          // wqkv (3M) | wo (1M) | w1 (4M) | w2 (4M)
__device__ float  g_bqkv[3072];                // packed bias
__device__ __half g_xh[ROWS*EMB];              // LN out (half)
__device__ __half g_qkvh[(size_t)ROWS*QKV_STR];// packed q|k|v (half)
__device__ __half g_ah[ROWS*EMB];              // attention out (half)
__device__ __half g_hh[ROWS*FF];               // MLP hidden (half)
__device__ float  g_scores[(size_t)BH*SEQ*SEQ];
__device__ __half g_ph[(size_t)BH*SEQ*SEQ];    // softmax probs (half)
__device__ float  g_x[ROWS*EMB];               // residual stream (fp32)

// ---------------- helpers ----------------
__device__ __forceinline__ void cp_async16(void* smem_dst, const void* gsrc) {
    unsigned s = (unsigned)__cvta_generic_to_shared(smem_dst);
    asm volatile("cp.async.cg.shared.global [%0], [%1], 16;\n" :: "r"(s), "l"(gsrc));
}
__device__ __forceinline__ void cp_commit() {
    asm volatile("cp.async.commit_group;\n");
}
__device__ __forceinline__ float gelu_exact(float y) {
    return 0.5f * y * (1.0f + erff(y * 0.70710678118654752f));
}
__device__ __forceinline__ void st_half4(__half* p, float4 v) {
    __half2* p2 = reinterpret_cast<__half2*>(p);
    p2[0] = __floats2half2_rn(v.x, v.y);
    p2[1] = __floats2half2_rn(v.z, v.w);
}

// ---------------- fused weight conversion / packing ----------------
// f4 index space (3145728 total):
//  [0, 786432): q,k,v  -> interleaved into wqkv [1024 rows x 768 f4]
//  [786432, 1048576): wo (direct)
//  [1048576, 2097152): w1 (direct)
//  [2097152, 3145728): w2 (direct)
__global__ void cvt_all(const float* __restrict__ wq, const float* __restrict__ wk,
                        const float* __restrict__ wv, const float* __restrict__ wo,
                        const float* __restrict__ w1, const float* __restrict__ w2,
                        __half* __restrict__ d) {
    size_t i = (size_t)blockIdx.x * blockDim.x + threadIdx.x;
    if (i < 786432) {
        int seg = (int)(i >> 18);              // 0,1,2
        size_t li = i & 262143;
        int r = (int)(li >> 8), c = (int)(li & 255);
        const float* src = seg == 0 ? wq : (seg == 1 ? wk : wv);
        float4 v = reinterpret_cast<const float4*>(src)[li];
        st_half4(d + ((size_t)r * 768 + seg * 256 + c) * 4, v);
    } else if (i < 1048576) {
        size_t li = i - 786432;
        float4 v = reinterpret_cast<const float4*>(wo)[li];
        st_half4(d + i * 4, v);
    } else if (i < 2097152) {
        size_t li = i - 1048576;
        float4 v = reinterpret_cast<const float4*>(w1)[li];
        st_half4(d + i * 4, v);
    } else {
        size_t li = i - 2097152;
        float4 v = reinterpret_cast<const float4*>(w2)[li];
        st_half4(d + i * 4, v);
    }
}

__global__ void cvt_bias(const float* __restrict__ bq, const float* __restrict__ bk,
                         const float* __restrict__ bv, float* __restrict__ dst) {
    int i = blockIdx.x * blockDim.x + threadIdx.x;   // 0..3071
    const float* s = i < 1024 ? bq : (i < 2048 ? bk : bv);
    dst[i] = s[i & 1023];
}

// ---------------- LayerNorm: fp32 in, half out ----------------
__global__ void ln_kernel(const float* __restrict__ in, const float* __restrict__ gam,
                          const float* __restrict__ bet, __half* __restrict__ out) {
    int row = blockIdx.x;
    int t = threadIdx.x;
    const float4* inr = reinterpret_cast<const float4*>(in + (size_t)row * EMB);
    float4 x = inr[t];
    float s  = x.x + x.y + x.z + x.w;
    float sq = x.x*x.x + x.y*x.y + x.z*x.z + x.w*x.w;
    #pragma unroll
    for (int o = 16; o > 0; o >>= 1) {
        s  += __shfl_xor_sync(0xffffffffu, s,  o);
        sq += __shfl_xor_sync(0xffffffffu, sq, o);
    }
    __shared__ float sa[8], sb[8];
    int w = t >> 5, l = t & 31;
    if (l == 0) { sa[w] = s; sb[w] = sq; }
    __syncthreads();
    s = 0.f; sq = 0.f;
    #pragma unroll
    for (int i = 0; i < 8; i++) { s += sa[i]; sq += sb[i]; }
    float mean = s * (1.0f / EMB);
    float var  = sq * (1.0f / EMB) - mean * mean;
    float rstd = rsqrtf(var + 1e-5f);
    float4 g4 = reinterpret_cast<const float4*>(gam)[t];
    float4 b4 = reinterpret_cast<const float4*>(bet)[t];
    float4 o4;
    o4.x = (x.x - mean) * rstd * g4.x + b4.x;
    o4.y = (x.y - mean) * rstd * g4.y + b4.y;
    o4.z = (x.z - mean) * rstd * g4.z + b4.z;
    o4.w = (x.w - mean) * rstd * g4.w + b4.w;
    st_half4(out + (size_t)row * EMB + t * 4, o4);
}

// ---------------- FP16 GEMM: 256x128 block, warp tile 64x64, BK=64 ----------------
// 8 warps as 4(m) x 2(n). Double-buffered cp.async. fp32 accum.
// EPI: 0 = +bias -> half    1 = +bias,GELU -> half    2 = +bias,+res -> float
#define ALD 72     // halves per A row
#define BLD 136    // halves per B row
#define ASTG_H (256*ALD)                 // halves
#define BSTG_H (64*BLD)
#define STG_BYTES ((ASTG_H + BSTG_H)*2)  // 54272
#define GEMM_SMEM (2*STG_BYTES)          // 108544

template<int EPI>
__global__ __launch_bounds__(256, 1)
void gemm_h(const __half* __restrict__ A, const __half* __restrict__ B,
            const float* __restrict__ bias, const float* __restrict__ res,
            void* __restrict__ Cout, int M, int N, int K) {
    extern __shared__ char smraw[];
    __half* As[2] = { (__half*)smraw, (__half*)(smraw + STG_BYTES) };
    __half* Bs[2] = { (__half*)smraw + ASTG_H, (__half*)(smraw + STG_BYTES) + ASTG_H };
    float* Cs = (float*)smraw;   // epilogue alias [128][132]

    const int m0 = blockIdx.y * 256;
    const int n0 = blockIdx.x * 128;
    const int tid = threadIdx.x;
    const int warp = tid >> 5;
    const int wm = warp >> 1;      // 0..3
    const int wn = warp & 1;       // 0..1

    wmma::fragment<wmma::accumulator, 16, 16, 16, float> acc[4][4];
    #pragma unroll
    for (int i = 0; i < 4; i++)
        #pragma unroll
        for (int j = 0; j < 4; j++)
            wmma::fill_fragment(acc[i][j], 0.0f);

    auto load_stage = [&](int st, int k0) {
        #pragma unroll
        for (int p = 0; p < 8; p++) {              // A: 256 rows x 8 chunks (8 halves)
            int idx = tid + p * 256;
            int r = idx >> 3, c = (idx & 7) << 3;
            cp_async16(As[st] + r * ALD + c, A + (size_t)(m0 + r) * K + k0 + c);
        }
        #pragma unroll
        for (int p = 0; p < 4; p++) {              // B: 64 rows x 16 chunks
            int idx = tid + p * 256;
            int r = idx >> 4, c = (idx & 15) << 3;
            cp_async16(Bs[st] + r * BLD + c, B + (size_t)(k0 + r) * N + n0 + c);
        }
        cp_commit();
    };

    const int NT = K >> 6;
    load_stage(0, 0);

    for (int kt = 0; kt < NT; kt++) {
        if (kt + 1 < NT) {
            load_stage((kt + 1) & 1, (kt + 1) << 6);
            asm volatile("cp.async.wait_group 1;\n");
        } else {
            asm volatile("cp.async.wait_group 0;\n");
        }
        __syncthreads();
        const __half* as = As[kt & 1];
        const __half* bs = Bs[kt & 1];
        #pragma unroll
        for (int ks = 0; ks < 4; ks++) {
            wmma::fragment<wmma::matrix_a, 16, 16, 16, __half, wmma::row_major> af[4];
            wmma::fragment<wmma::matrix_b, 16, 16, 16, __half, wmma::row_major> bf[4];
            #pragma unroll
            for (int i = 0; i < 4; i++)
                wmma::load_matrix_sync(af[i], as + (wm * 64 + i * 16) * ALD + ks * 16, ALD);
            #pragma unroll
            for (int j = 0; j < 4; j++)
                wmma::load_matrix_sync(bf[j], bs + (ks * 16) * BLD + wn * 64 + j * 16, BLD);
            #pragma unroll
            for (int i = 0; i < 4; i++)
                #pragma unroll
                for (int j = 0; j < 4; j++)
                    wmma::mma_sync(acc[i][j], af[i], bf[j], acc[i][j]);
        }
        __syncthreads();
    }

    // epilogue: two passes of 128 rows each through smem
    #pragma unroll
    for (int pass = 0; pass < 2; pass++) {
        if ((wm >> 1) == pass) {
            int rbase = (wm & 1) * 64;
            #pragma unroll
            for (int i = 0; i < 4; i++)
                #pragma unroll
                for (int j = 0; j < 4; j++)
                    wmma::store_matrix_sync(Cs + (rbase + i * 16) * 132 + wn * 64 + j * 16,
                                            acc[i][j], 132, wmma::mem_row_major);
        }
        __syncthreads();
        #pragma unroll
        for (int p = 0; p < 16; p++) {
            int idx = tid + p * 256;              // 128 rows x 32 float4
            int r = idx >> 5, c = (idx & 31) << 2;
            int grow = m0 + pass * 128 + r;
            float4 v = *reinterpret_cast<const float4*>(Cs + r * 132 + c);
            float4 b = *reinterpret_cast<const float4*>(bias + n0 + c);
            v.x += b.x; v.y += b.y; v.z += b.z; v.w += b.w;
            if (EPI == 1) {
                v.x = gelu_exact(v.x); v.y = gelu_exact(v.y);
                v.z = gelu_exact(v.z); v.w = gelu_exact(v.w);
            }
            if (EPI == 2) {
                float4 rr = *reinterpret_cast<const float4*>(res + (size_t)grow * N + n0 + c);
                v.x += rr.x; v.y += rr.y; v.z += rr.z; v.w += rr.w;
                *reinterpret_cast<float4*>((float*)Cout + (size_t)grow * N + n0 + c) = v;
            } else {
                st_half4((__half*)Cout + (size_t)grow * N + n0 + c, v);
            }
        }
        __syncthreads();
    }
}

// ---------------- attention scores = (Q K^T) * 1/8, fp16 wmma ----------------
// q,k packed in g_qkvh with row stride QKV_STR; k at col offset 1024.
#define QLD 72
#define SCORES_SMEM (2*128*QLD*2)   // 36864

__global__ __launch_bounds__(256, 2)
void scores_h(const __half* __restrict__ qkv, float* __restrict__ s) {
    extern __shared__ char smraw[];
    __half* Qs = (__half*)smraw;              // [128][QLD]
    __half* Ks = (__half*)smraw + 128*QLD;    // [128][QLD]
    int bh = blockIdx.z;
    int b = bh >> 4, h = bh & 15;
    int q0 = blockIdx.y * 128, k0 = blockIdx.x * 128;
    int tid = threadIdx.x;
    const __half* qbase = qkv + (size_t)(b * SEQ + q0) * QKV_STR + h * HDIM;
    const __half* kbase = qkv + (size_t)(b * SEQ + k0) * QKV_STR + 1024 + h * HDIM;
    #pragma unroll
    for (int p = 0; p < 4; p++) {
        int idx = tid + p * 256;              // 128 rows x 8 chunks (8 halves)
        int r = idx >> 3, c = (idx & 7) << 3;
        *reinterpret_cast<float4*>(Qs + r * QLD + c) =
            *reinterpret_cast<const float4*>(qbase + (size_t)r * QKV_STR + c);
        *reinterpret_cast<float4*>(Ks + r * QLD + c) =
            *reinterpret_cast<const float4*>(kbase + (size_t)r * QKV_STR + c);
    }
    __syncthreads();

    int warp = tid >> 5, wm = warp >> 2, wn = warp & 3;
    wmma::fragment<wmma::accumulator, 16, 16, 16, float> acc[4][2];
    #pragma unroll
    for (int i = 0; i < 4; i++)
        #pragma unroll
        for (int j = 0; j < 2; j++)
            wmma::fill_fragment(acc[i][j], 0.0f);

    #pragma unroll
    for (int ks = 0; ks < 4; ks++) {
        wmma::fragment<wmma::matrix_a, 16, 16, 16, __half, wmma::row_major> af[4];
        wmma::fragment<wmma::matrix_b, 16, 16, 16, __half, wmma::col_major> bf[2];
        #pragma unroll
        for (int i = 0; i < 4; i++)
            wmma::load_matrix_sync(af[i], Qs + (wm * 64 + i * 16) * QLD + ks * 16, QLD);
        #pragma unroll
        for (int j = 0; j < 2; j++)
            wmma::load_matrix_sync(bf[j], Ks + (wn * 32 + j * 16) * QLD + ks * 16, QLD);
        #pragma unroll
        for (int i = 0; i < 4; i++)
            #pragma unroll
            for (int j = 0; j < 2; j++)
                wmma::mma_sync(acc[i][j], af[i], bf[j], acc[i][j]);
    }

    #pragma unroll
    for (int i = 0; i < 4; i++)
        #pragma unroll
        for (int j = 0; j < 2; j++) {
            #pragma unroll
            for (int e = 0; e < acc[i][j].num_elements; e++)
                acc[i][j].x[e] *= 0.125f;
            wmma::store_matrix_sync(
                s + ((size_t)bh * SEQ + q0 + wm * 64 + i * 16) * SEQ + k0 + wn * 32 + j * 16,
                acc[i][j], SEQ, wmma::mem_row_major);
        }
}

// ---------------- softmax: fp32 scores in, half probs out ----------------
__global__ void softmax_kernel(const float* __restrict__ s, __half* __restrict__ ph) {
    size_t row = blockIdx.x;
    const float* p = s + row * SEQ;
    int t = threadIdx.x;
    float4 x = reinterpret_cast<const float4*>(p)[t];
    float m = fmaxf(fmaxf(x.x, x.y), fmaxf(x.z, x.w));
    #pragma unroll
    for (int o = 16; o > 0; o >>= 1) m = fmaxf(m, __shfl_xor_sync(0xffffffffu, m, o));
    __shared__ float sm[4], ss[4];
    int w = t >> 5, l = t & 31;
    if (l == 0) sm[w] = m;
    __syncthreads();
    m = fmaxf(fmaxf(sm[0], sm[1]), fmaxf(sm[2], sm[3]));
    x.x = __expf(x.x - m); x.y = __expf(x.y - m);
    x.z = __expf(x.z - m); x.w = __expf(x.w - m);
    float sum = x.x + x.y + x.z + x.w;
    #pragma unroll
    for (int o = 16; o > 0; o >>= 1) sum += __shfl_xor_sync(0xffffffffu, sum, o);
    if (l == 0) ss[w] = sum;
    __syncthreads();
    sum = ss[0] + ss[1] + ss[2] + ss[3];
    float inv = 1.0f / sum;
    x.x *= inv; x.y *= inv; x.z *= inv; x.w *= inv;
    st_half4(ph + row * SEQ + t * 4, x);
}

// ---------------- AV: attn = P V, fp16 wmma, half out ----------------
// v packed in g_qkvh at col offset 2048, row stride QKV_STR.
#define AV_SMEM 34816   // max(Ps+Vs = 27648, Cs 128*68*4 = 34816)

__global__ __launch_bounds__(256, 2)
void av_h(const __half* __restrict__ ph, const __half* __restrict__ qkv,
          __half* __restrict__ o) {
    extern __shared__ char smraw[];
    __half* Ps = (__half*)smraw;              // [128][QLD]
    __half* Vs = (__half*)smraw + 128*QLD;    // [64][QLD]
    float* Cs = (float*)smraw;                // epilogue alias [128][68]
    int bh = blockIdx.y;
    int b = bh >> 4, h = bh & 15;
    int q0 = blockIdx.x * 128;
    int tid = threadIdx.x;
    int warp = tid >> 5, wm = warp >> 1, wn = warp & 1;
    const __half* vbase = qkv + (size_t)b * SEQ * QKV_STR + 2048 + h * HDIM;

    wmma::fragment<wmma::accumulator, 16, 16, 16, float> acc[2][2];
    #pragma unroll
    for (int i = 0; i < 2; i++)
        #pragma unroll
        for (int j = 0; j < 2; j++)
            wmma::fill_fragment(acc[i][j], 0.0f);

    for (int kc = 0; kc < SEQ; kc += 64) {
        #pragma unroll
        for (int p = 0; p < 4; p++) {          // P: 128 rows x 8 chunks
            int idx = tid + p * 256;
            int r = idx >> 3, c = (idx & 7) << 3;
            *reinterpret_cast<float4*>(Ps + r * QLD + c) =
                *reinterpret_cast<const float4*>(ph + ((size_t)bh * SEQ + q0 + r) * SEQ + kc + c);
        }
        #pragma unroll
        for (int p = 0; p < 2; p++) {          // V: 64 rows x 8 chunks
            int idx = tid + p * 256;
            int r = idx >> 3, c = (idx & 7) << 3;
            *reinterpret_cast<float4*>(Vs + r * QLD + c) =
                *reinterpret_cast<const float4*>(vbase + (size_t)(kc + r) * QKV_STR + c);
        }
        __syncthreads();
        #pragma unroll
        for (int ks = 0; ks < 4; ks++) {
            wmma::fragment<wmma::matrix_a, 16, 16, 16, __half, wmma::row_major> af[2];
            wmma::fragment<wmma::matrix_b, 16, 16, 16, __half, wmma::row_major> bf[2];
            #pragma unroll
            for (int i = 0; i < 2; i++)
                wmma::load_matrix_sync(af[i], Ps + (wm * 32 + i * 16) * QLD + ks * 16, QLD);
            #pragma unroll
            for (int j = 0; j < 2; j++)
                wmma::load_matrix_sync(bf[j], Vs + (ks * 16) * QLD + wn * 32 + j * 16, QLD);
            #pragma unroll
            for (int i = 0; i < 2; i++)
                #pragma unroll
                for (int j = 0; j < 2; j++)
                    wmma::mma_sync(acc[i][j], af[i], bf[j], acc[i][j]);
        }
        __syncthreads();
    }

    #pragma unroll
    for (int i = 0; i < 2; i++)
        #pragma unroll
        for (int j = 0; j < 2; j++)
            wmma::store_matrix_sync(Cs + (wm * 32 + i * 16) * 68 + wn * 32 + j * 16,
                                    acc[i][j], 68, wmma::mem_row_major);
    __syncthreads();
    #pragma unroll
    for (int p = 0; p < 8; p++) {
        int idx = tid + p * 256;              // 128 rows x 16 float4
        int r = idx >> 4, c = (idx & 15) << 2;
        float4 vv = *reinterpret_cast<const float4*>(Cs + r * 68 + c);
        st_half4(o + (size_t)(b * SEQ + q0 + r) * EMB + h * HDIM + c, vv);
    }
}

// ---------------- driver ----------------
extern "C" void kernel_launch(void* const* d_in, const int* in_sizes, int n_in,
                              void* d_out, int out_size) {
    const float* input = (const float*)d_in[0];
    const float* ln1_g = (const float*)d_in[1];
    const float* ln1_b = (const float*)d_in[2];
    const float* wq    = (const float*)d_in[3];
    const float* bq    = (const float*)d_in[4];
    const float* wk    = (const float*)d_in[5];
    const float* bk    = (const float*)d_in[6];
    const float* wv    = (const float*)d_in[7];
    const float* bv    = (const float*)d_in[8];
    const float* wo    = (const float*)d_in[9];
    const float* bo    = (const float*)d_in[10];
    const float* ln2_g = (const float*)d_in[11];
    const float* ln2_b = (const float*)d_in[12];
    const float* w1    = (const float*)d_in[13];
    const float* b1    = (const float*)d_in[14];
    const float* w2    = (const float*)d_in[15];
    const float* b2    = (const float*)d_in[16];
    float* out = (float*)d_out;

    __half *wH, *xh, *qkvh, *ah, *hh, *phh;
    float *scores, *x, *bqkv;
    cudaGetSymbolAddress((void**)&wH,     g_wH);
    cudaGetSymbolAddress((void**)&bqkv,   g_bqkv);
    cudaGetSymbolAddress((void**)&xh,     g_xh);
    cudaGetSymbolAddress((void**)&qkvh,   g_qkvh);
    cudaGetSymbolAddress((void**)&ah,     g_ah);
    cudaGetSymbolAddress((void**)&hh,     g_hh);
    cudaGetSymbolAddress((void**)&phh,    g_ph);
    cudaGetSymbolAddress((void**)&scores, g_scores);
    cudaGetSymbolAddress((void**)&x,      g_x);

    __half* wqkvH = wH;                     // [1024,3072]
    __half* woH   = wH + 3145728;           // [1024,1024]
    __half* w1H   = wH + 4194304;           // [1024,4096]
    __half* w2H   = wH + 8388608;           // [4096,1024]

    cudaFuncSetAttribute(gemm_h<0>, cudaFuncAttributeMaxDynamicSharedMemorySize, GEMM_SMEM);
    cudaFuncSetAttribute(gemm_h<1>, cudaFuncAttributeMaxDynamicSharedMemorySize, GEMM_SMEM);
    cudaFuncSetAttribute(gemm_h<2>, cudaFuncAttributeMaxDynamicSharedMemorySize, GEMM_SMEM);
    cudaFuncSetAttribute(scores_h,  cudaFuncAttributeMaxDynamicSharedMemorySize, SCORES_SMEM);
    cudaFuncSetAttribute(av_h,      cudaFuncAttributeMaxDynamicSharedMemorySize, AV_SMEM);

    // 0) pack + convert weights (single pass) and biases
    cvt_all<<<12288, 256>>>(wq, wk, wv, wo, w1, w2, wH);
    cvt_bias<<<12, 256>>>(bq, bk, bv, bqkv);

    // 1) LN1 -> half
    ln_kernel<<<ROWS, 256>>>(input, ln1_g, ln1_b, xh);
    // 2) fused QKV projection (one GEMM, N=3072)
    gemm_h<0><<<dim3(QKV_STR/128, ROWS/256), 256, GEMM_SMEM>>>(
        xh, wqkvH, bqkv, nullptr, qkvh, ROWS, QKV_STR, EMB);
    // 3) attention
    scores_h<<<dim3(4, 4, BH), 256, SCORES_SMEM>>>(qkvh, scores);
    softmax_kernel<<<BH * SEQ, 128>>>(scores, phh);
    av_h<<<dim3(4, BH), 256, AV_SMEM>>>(phh, qkvh, ah);
    // 4) output projection + bias + residual (fp32 out)
    gemm_h<2><<<dim3(EMB/128, ROWS/256), 256, GEMM_SMEM>>>(
        ah, woH, bo, input, x, ROWS, EMB, EMB);
    // 5) LN2 -> half
    ln_kernel<<<ROWS, 256>>>(x, ln2_g, ln2_b, xh);
    // 6) MLP up + bias + GELU -> half
    gemm_h<1><<<dim3(FF/128, ROWS/256), 256, GEMM_SMEM>>>(
        xh, w1H, b1, nullptr, hh, ROWS, FF, EMB);
    // 7) MLP down + bias + residual -> out (fp32)
    gemm_h<2><<<dim3(EMB/128, ROWS/256), 256, GEMM_SMEM>>>(
        hh, w2H, b2, x, out, ROWS, EMB, FF);
}

// round 13
// speedup vs baseline: 1.2950x; 1.2155x over previous
#include <cuda_runtime.h>
#include <cuda_fp16.h>
#include <mma.h>
#include <math.h>
#include <cstdint>

using namespace nvcuda;

// Problem dims
#define BATCH 16
#define SEQ   512
#define EMB   1024
#define FF    4096
#define HEADS 16
#define HDIM  64
#define ROWS  (BATCH*SEQ)        // 8192
#define BH    (BATCH*HEADS)      // 256
#define QKV_STR 3072             // packed q|k|v row stride

// ---------------- scratch (device globals; no allocation allowed) ----------------
__device__ __half g_wH[12*1024*1024];          // wqkv (3M) | wo (1M) | w1 (4M) | w2 (4M)
__device__ float  g_bqkv[3072];                // packed bias
__device__ __half g_xh[ROWS*EMB];              // LN out (half)
__device__ __half g_qkvh[(size_t)ROWS*QKV_STR];// packed q|k|v (half)
__device__ __half g_ah[ROWS*EMB];              // attention out (half)
__device__ __half g_hh[ROWS*FF];               // MLP hidden (half)
__device__ float  g_scores[(size_t)BH*SEQ*SEQ];
__device__ __half g_ph[(size_t)BH*SEQ*SEQ];    // softmax probs (half)
__device__ float  g_x[ROWS*EMB];               // residual stream (fp32)

// ---------------- helpers ----------------
__device__ __forceinline__ void cp_async16(void* smem_dst, const void* gsrc) {
    unsigned s = (unsigned)__cvta_generic_to_shared(smem_dst);
    asm volatile("cp.async.cg.shared.global [%0], [%1], 16;\n" :: "r"(s), "l"(gsrc));
}
__device__ __forceinline__ void cp_commit() {
    asm volatile("cp.async.commit_group;\n");
}
__device__ __forceinline__ float gelu_exact(float y) {
    return 0.5f * y * (1.0f + erff(y * 0.70710678118654752f));
}
__device__ __forceinline__ void st_half4(__half* p, float4 v) {
    __half2* p2 = reinterpret_cast<__half2*>(p);
    p2[0] = __floats2half2_rn(v.x, v.y);
    p2[1] = __floats2half2_rn(v.z, v.w);
}

// ---------------- fused weight conversion / packing ----------------
__global__ void cvt_all(const float* __restrict__ wq, const float* __restrict__ wk,
                        const float* __restrict__ wv, const float* __restrict__ wo,
                        const float* __restrict__ w1, const float* __restrict__ w2,
                        __half* __restrict__ d) {
    size_t i = (size_t)blockIdx.x * blockDim.x + threadIdx.x;
    if (i < 786432) {
        int seg = (int)(i >> 18);              // 0,1,2
        size_t li = i & 262143;
        int r = (int)(li >> 8), c = (int)(li & 255);
        const float* src = seg == 0 ? wq : (seg == 1 ? wk : wv);
        float4 v = reinterpret_cast<const float4*>(src)[li];
        st_half4(d + ((size_t)r * 768 + seg * 256 + c) * 4, v);
    } else if (i < 1048576) {
        size_t li = i - 786432;
        float4 v = reinterpret_cast<const float4*>(wo)[li];
        st_half4(d + i * 4, v);
    } else if (i < 2097152) {
        size_t li = i - 1048576;
        float4 v = reinterpret_cast<const float4*>(w1)[li];
        st_half4(d + i * 4, v);
    } else {
        size_t li = i - 2097152;
        float4 v = reinterpret_cast<const float4*>(w2)[li];
        st_half4(d + i * 4, v);
    }
}

__global__ void cvt_bias(const float* __restrict__ bq, const float* __restrict__ bk,
                         const float* __restrict__ bv, float* __restrict__ dst) {
    int i = blockIdx.x * blockDim.x + threadIdx.x;   // 0..3071
    const float* s = i < 1024 ? bq : (i < 2048 ? bk : bv);
    dst[i] = s[i & 1023];
}

// ---------------- LayerNorm: fp32 in, half out ----------------
__global__ void ln_kernel(const float* __restrict__ in, const float* __restrict__ gam,
                          const float* __restrict__ bet, __half* __restrict__ out) {
    int row = blockIdx.x;
    int t = threadIdx.x;
    const float4* inr = reinterpret_cast<const float4*>(in + (size_t)row * EMB);
    float4 x = inr[t];
    float s  = x.x + x.y + x.z + x.w;
    float sq = x.x*x.x + x.y*x.y + x.z*x.z + x.w*x.w;
    #pragma unroll
    for (int o = 16; o > 0; o >>= 1) {
        s  += __shfl_xor_sync(0xffffffffu, s,  o);
        sq += __shfl_xor_sync(0xffffffffu, sq, o);
    }
    __shared__ float sa[8], sb[8];
    int w = t >> 5, l = t & 31;
    if (l == 0) { sa[w] = s; sb[w] = sq; }
    __syncthreads();
    s = 0.f; sq = 0.f;
    #pragma unroll
    for (int i = 0; i < 8; i++) { s += sa[i]; sq += sb[i]; }
    float mean = s * (1.0f / EMB);
    float var  = sq * (1.0f / EMB) - mean * mean;
    float rstd = rsqrtf(var + 1e-5f);
    float4 g4 = reinterpret_cast<const float4*>(gam)[t];
    float4 b4 = reinterpret_cast<const float4*>(bet)[t];
    float4 o4;
    o4.x = (x.x - mean) * rstd * g4.x + b4.x;
    o4.y = (x.y - mean) * rstd * g4.y + b4.y;
    o4.z = (x.z - mean) * rstd * g4.z + b4.z;
    o4.w = (x.w - mean) * rstd * g4.w + b4.w;
    st_half4(out + (size_t)row * EMB + t * 4, o4);
}

// ---------------- FP16 GEMM: 128x128 block, warp 64x32, BK=64, 3-stage pipeline ----
// 8 warps as 2(m) x 4(n). fp32 accum.
// EPI: 0 = +bias -> half    1 = +bias,GELU -> half    2 = +bias,+res -> float
#define ALD 72     // halves per A row
#define BLD 136    // halves per B row
#define ASTG_H (128*ALD)
#define BSTG_H (64*BLD)
#define STG_BYTES ((ASTG_H + BSTG_H)*2)  // 35840
#define GEMM_SMEM (3*STG_BYTES)          // 107520

template<int EPI>
__global__ __launch_bounds__(256, 2)
void gemm_h(const __half* __restrict__ A, const __half* __restrict__ B,
            const float* __restrict__ bias, const float* __restrict__ res,
            void* __restrict__ Cout, int M, int N, int K) {
    extern __shared__ char smraw[];
    float* Cs = (float*)smraw;   // epilogue alias [128][132]

    const int m0 = blockIdx.y * 128;
    const int n0 = blockIdx.x * 128;
    const int tid = threadIdx.x;
    const int warp = tid >> 5;
    const int wm = warp >> 2;      // 0..1
    const int wn = warp & 3;       // 0..3

    wmma::fragment<wmma::accumulator, 16, 16, 16, float> acc[4][2];
    #pragma unroll
    for (int i = 0; i < 4; i++)
        #pragma unroll
        for (int j = 0; j < 2; j++)
            wmma::fill_fragment(acc[i][j], 0.0f);

    auto load_stage = [&](int st, int kc) {
        __half* as = (__half*)(smraw + st * STG_BYTES);
        __half* bs = as + ASTG_H;
        int k0 = kc << 6;
        #pragma unroll
        for (int p = 0; p < 4; p++) {              // A: 128 rows x 8 chunks (8 halves)
            int idx = tid + p * 256;
            int r = idx >> 3, c = (idx & 7) << 3;
            cp_async16(as + r * ALD + c, A + (size_t)(m0 + r) * K + k0 + c);
        }
        #pragma unroll
        for (int p = 0; p < 4; p++) {              // B: 64 rows x 16 chunks
            int idx = tid + p * 256;
            int r = idx >> 4, c = (idx & 15) << 3;
            cp_async16(bs + r * BLD + c, B + (size_t)(k0 + r) * N + n0 + c);
        }
        cp_commit();
    };

    const int NT = K >> 6;
    int st = 0;                    // stage of chunk kt
    load_stage(0, 0);
    load_stage(1, 1);

    for (int kt = 0; kt < NT; kt++) {
        if (kt < NT - 1) asm volatile("cp.async.wait_group 1;\n");
        else             asm volatile("cp.async.wait_group 0;\n");
        __syncthreads();
        // issue next prefetch AFTER barrier: its stage was last read at kt-1 (safe)
        if (kt + 2 < NT) {
            int st2 = st + 2; if (st2 >= 3) st2 -= 3;
            load_stage(st2, kt + 2);
        }
        const __half* as = (const __half*)(smraw + st * STG_BYTES);
        const __half* bs = as + ASTG_H;
        #pragma unroll
        for (int ks = 0; ks < 4; ks++) {
            wmma::fragment<wmma::matrix_a, 16, 16, 16, __half, wmma::row_major> af[4];
            wmma::fragment<wmma::matrix_b, 16, 16, 16, __half, wmma::row_major> bf[2];
            #pragma unroll
            for (int i = 0; i < 4; i++)
                wmma::load_matrix_sync(af[i], as + (wm * 64 + i * 16) * ALD + ks * 16, ALD);
            #pragma unroll
            for (int j = 0; j < 2; j++)
                wmma::load_matrix_sync(bf[j], bs + (ks * 16) * BLD + wn * 32 + j * 16, BLD);
            #pragma unroll
            for (int i = 0; i < 4; i++)
                #pragma unroll
                for (int j = 0; j < 2; j++)
                    wmma::mma_sync(acc[i][j], af[i], bf[j], acc[i][j]);
        }
        __syncthreads();
        if (++st == 3) st = 0;
    }

    // epilogue via smem
    #pragma unroll
    for (int i = 0; i < 4; i++)
        #pragma unroll
        for (int j = 0; j < 2; j++)
            wmma::store_matrix_sync(Cs + (wm * 64 + i * 16) * 132 + wn * 32 + j * 16,
                                    acc[i][j], 132, wmma::mem_row_major);
    __syncthreads();

    #pragma unroll
    for (int p = 0; p < 16; p++) {
        int idx = tid + p * 256;              // 128 rows x 32 float4
        int r = idx >> 5, c = (idx & 31) << 2;
        float4 v = *reinterpret_cast<const float4*>(Cs + r * 132 + c);
        float4 b = *reinterpret_cast<const float4*>(bias + n0 + c);
        v.x += b.x; v.y += b.y; v.z += b.z; v.w += b.w;
        if (EPI == 1) {
            v.x = gelu_exact(v.x); v.y = gelu_exact(v.y);
            v.z = gelu_exact(v.z); v.w = gelu_exact(v.w);
        }
        if (EPI == 2) {
            float4 rr = *reinterpret_cast<const float4*>(res + (size_t)(m0 + r) * N + n0 + c);
            v.x += rr.x; v.y += rr.y; v.z += rr.z; v.w += rr.w;
            *reinterpret_cast<float4*>((float*)Cout + (size_t)(m0 + r) * N + n0 + c) = v;
        } else {
            st_half4((__half*)Cout + (size_t)(m0 + r) * N + n0 + c, v);
        }
    }
}

// ---------------- attention scores = (Q K^T) * 1/8, fp16 wmma ----------------
#define QLD 72
#define SCORES_SMEM (2*128*QLD*2)   // 36864

__global__ __launch_bounds__(256, 2)
void scores_h(const __half* __restrict__ qkv, float* __restrict__ s) {
    extern __shared__ char smraw[];
    __half* Qs = (__half*)smraw;              // [128][QLD]
    __half* Ks = (__half*)smraw + 128*QLD;    // [128][QLD]
    int bh = blockIdx.z;
    int b = bh >> 4, h = bh & 15;
    int q0 = blockIdx.y * 128, k0 = blockIdx.x * 128;
    int tid = threadIdx.x;
    const __half* qbase = qkv + (size_t)(b * SEQ + q0) * QKV_STR + h * HDIM;
    const __half* kbase = qkv + (size_t)(b * SEQ + k0) * QKV_STR + 1024 + h * HDIM;
    #pragma unroll
    for (int p = 0; p < 4; p++) {
        int idx = tid + p * 256;              // 128 rows x 8 chunks (8 halves)
        int r = idx >> 3, c = (idx & 7) << 3;
        *reinterpret_cast<float4*>(Qs + r * QLD + c) =
            *reinterpret_cast<const float4*>(qbase + (size_t)r * QKV_STR + c);
        *reinterpret_cast<float4*>(Ks + r * QLD + c) =
            *reinterpret_cast<const float4*>(kbase + (size_t)r * QKV_STR + c);
    }
    __syncthreads();

    int warp = tid >> 5, wm = warp >> 2, wn = warp & 3;
    wmma::fragment<wmma::accumulator, 16, 16, 16, float> acc[4][2];
    #pragma unroll
    for (int i = 0; i < 4; i++)
        #pragma unroll
        for (int j = 0; j < 2; j++)
            wmma::fill_fragment(acc[i][j], 0.0f);

    #pragma unroll
    for (int ks = 0; ks < 4; ks++) {
        wmma::fragment<wmma::matrix_a, 16, 16, 16, __half, wmma::row_major> af[4];
        wmma::fragment<wmma::matrix_b, 16, 16, 16, __half, wmma::col_major> bf[2];
        #pragma unroll
        for (int i = 0; i < 4; i++)
            wmma::load_matrix_sync(af[i], Qs + (wm * 64 + i * 16) * QLD + ks * 16, QLD);
        #pragma unroll
        for (int j = 0; j < 2; j++)
            wmma::load_matrix_sync(bf[j], Ks + (wn * 32 + j * 16) * QLD + ks * 16, QLD);
        #pragma unroll
        for (int i = 0; i < 4; i++)
            #pragma unroll
            for (int j = 0; j < 2; j++)
                wmma::mma_sync(acc[i][j], af[i], bf[j], acc[i][j]);
    }

    #pragma unroll
    for (int i = 0; i < 4; i++)
        #pragma unroll
        for (int j = 0; j < 2; j++) {
            #pragma unroll
            for (int e = 0; e < acc[i][j].num_elements; e++)
                acc[i][j].x[e] *= 0.125f;
            wmma::store_matrix_sync(
                s + ((size_t)bh * SEQ + q0 + wm * 64 + i * 16) * SEQ + k0 + wn * 32 + j * 16,
                acc[i][j], SEQ, wmma::mem_row_major);
        }
}

// ---------------- softmax: fp32 scores in, half probs out ----------------
__global__ void softmax_kernel(const float* __restrict__ s, __half* __restrict__ ph) {
    size_t row = blockIdx.x;
    const float* p = s + row * SEQ;
    int t = threadIdx.x;
    float4 x = reinterpret_cast<const float4*>(p)[t];
    float m = fmaxf(fmaxf(x.x, x.y), fmaxf(x.z, x.w));
    #pragma unroll
    for (int o = 16; o > 0; o >>= 1) m = fmaxf(m, __shfl_xor_sync(0xffffffffu, m, o));
    __shared__ float sm[4], ss[4];
    int w = t >> 5, l = t & 31;
    if (l == 0) sm[w] = m;
    __syncthreads();
    m = fmaxf(fmaxf(sm[0], sm[1]), fmaxf(sm[2], sm[3]));
    x.x = __expf(x.x - m); x.y = __expf(x.y - m);
    x.z = __expf(x.z - m); x.w = __expf(x.w - m);
    float sum = x.x + x.y + x.z + x.w;
    #pragma unroll
    for (int o = 16; o > 0; o >>= 1) sum += __shfl_xor_sync(0xffffffffu, sum, o);
    if (l == 0) ss[w] = sum;
    __syncthreads();
    sum = ss[0] + ss[1] + ss[2] + ss[3];
    float inv = 1.0f / sum;
    x.x *= inv; x.y *= inv; x.z *= inv; x.w *= inv;
    st_half4(ph + row * SEQ + t * 4, x);
}

// ---------------- AV: attn = P V, fp16 wmma, half out ----------------
#define AV_SMEM 34816   // max(Ps+Vs = 27648, Cs 128*68*4 = 34816)

__global__ __launch_bounds__(256, 2)
void av_h(const __half* __restrict__ ph, const __half* __restrict__ qkv,
          __half* __restrict__ o) {
    extern __shared__ char smraw[];
    __half* Ps = (__half*)smraw;              // [128][QLD]
    __half* Vs = (__half*)smraw + 128*QLD;    // [64][QLD]
    float* Cs = (float*)smraw;                // epilogue alias [128][68]
    int bh = blockIdx.y;
    int b = bh >> 4, h = bh & 15;
    int q0 = blockIdx.x * 128;
    int tid = threadIdx.x;
    int warp = tid >> 5, wm = warp >> 1, wn = warp & 1;
    const __half* vbase = qkv + (size_t)b * SEQ * QKV_STR + 2048 + h * HDIM;

    wmma::fragment<wmma::accumulator, 16, 16, 16, float> acc[2][2];
    #pragma unroll
    for (int i = 0; i < 2; i++)
        #pragma unroll
        for (int j = 0; j < 2; j++)
            wmma::fill_fragment(acc[i][j], 0.0f);

    for (int kc = 0; kc < SEQ; kc += 64) {
        #pragma unroll
        for (int p = 0; p < 4; p++) {          // P: 128 rows x 8 chunks
            int idx = tid + p * 256;
            int r = idx >> 3, c = (idx & 7) << 3;
            *reinterpret_cast<float4*>(Ps + r * QLD + c) =
                *reinterpret_cast<const float4*>(ph + ((size_t)bh * SEQ + q0 + r) * SEQ + kc + c);
        }
        #pragma unroll
        for (int p = 0; p < 2; p++) {          // V: 64 rows x 8 chunks
            int idx = tid + p * 256;
            int r = idx >> 3, c = (idx & 7) << 3;
            *reinterpret_cast<float4*>(Vs + r * QLD + c) =
                *reinterpret_cast<const float4*>(vbase + (size_t)(kc + r) * QKV_STR + c);
        }
        __syncthreads();
        #pragma unroll
        for (int ks = 0; ks < 4; ks++) {
            wmma::fragment<wmma::matrix_a, 16, 16, 16, __half, wmma::row_major> af[2];
            wmma::fragment<wmma::matrix_b, 16, 16, 16, __half, wmma::row_major> bf[2];
            #pragma unroll
            for (int i = 0; i < 2; i++)
                wmma::load_matrix_sync(af[i], Ps + (wm * 32 + i * 16) * QLD + ks * 16, QLD);
            #pragma unroll
            for (int j = 0; j < 2; j++)
                wmma::load_matrix_sync(bf[j], Vs + (ks * 16) * QLD + wn * 32 + j * 16, QLD);
            #pragma unroll
            for (int i = 0; i < 2; i++)
                #pragma unroll
                for (int j = 0; j < 2; j++)
                    wmma::mma_sync(acc[i][j], af[i], bf[j], acc[i][j]);
        }
        __syncthreads();
    }

    #pragma unroll
    for (int i = 0; i < 2; i++)
        #pragma unroll
        for (int j = 0; j < 2; j++)
            wmma::store_matrix_sync(Cs + (wm * 32 + i * 16) * 68 + wn * 32 + j * 16,
                                    acc[i][j], 68, wmma::mem_row_major);
    __syncthreads();
    #pragma unroll
    for (int p = 0; p < 8; p++) {
        int idx = tid + p * 256;              // 128 rows x 16 float4
        int r = idx >> 4, c = (idx & 15) << 2;
        float4 vv = *reinterpret_cast<const float4*>(Cs + r * 68 + c);
        st_half4(o + (size_t)(b * SEQ + q0 + r) * EMB + h * HDIM + c, vv);
    }
}

// ---------------- driver ----------------
extern "C" void kernel_launch(void* const* d_in, const int* in_sizes, int n_in,
                              void* d_out, int out_size) {
    const float* input = (const float*)d_in[0];
    const float* ln1_g = (const float*)d_in[1];
    const float* ln1_b = (const float*)d_in[2];
    const float* wq    = (const float*)d_in[3];
    const float* bq    = (const float*)d_in[4];
    const float* wk    = (const float*)d_in[5];
    const float* bk    = (const float*)d_in[6];
    const float* wv    = (const float*)d_in[7];
    const float* bv    = (const float*)d_in[8];
    const float* wo    = (const float*)d_in[9];
    const float* bo    = (const float*)d_in[10];
    const float* ln2_g = (const float*)d_in[11];
    const float* ln2_b = (const float*)d_in[12];
    const float* w1    = (const float*)d_in[13];
    const float* b1    = (const float*)d_in[14];
    const float* w2    = (const float*)d_in[15];
    const float* b2    = (const float*)d_in[16];
    float* out = (float*)d_out;

    __half *wH, *xh, *qkvh, *ah, *hh, *phh;
    float *scores, *x, *bqkv;
    cudaGetSymbolAddress((void**)&wH,     g_wH);
    cudaGetSymbolAddress((void**)&bqkv,   g_bqkv);
    cudaGetSymbolAddress((void**)&xh,     g_xh);
    cudaGetSymbolAddress((void**)&qkvh,   g_qkvh);
    cudaGetSymbolAddress((void**)&ah,     g_ah);
    cudaGetSymbolAddress((void**)&hh,     g_hh);
    cudaGetSymbolAddress((void**)&phh,    g_ph);
    cudaGetSymbolAddress((void**)&scores, g_scores);
    cudaGetSymbolAddress((void**)&x,      g_x);

    __half* wqkvH = wH;                     // [1024,3072]
    __half* woH   = wH + 3145728;           // [1024,1024]
    __half* w1H   = wH + 4194304;           // [1024,4096]
    __half* w2H   = wH + 8388608;           // [4096,1024]

    cudaFuncSetAttribute(gemm_h<0>, cudaFuncAttributeMaxDynamicSharedMemorySize, GEMM_SMEM);
    cudaFuncSetAttribute(gemm_h<1>, cudaFuncAttributeMaxDynamicSharedMemorySize, GEMM_SMEM);
    cudaFuncSetAttribute(gemm_h<2>, cudaFuncAttributeMaxDynamicSharedMemorySize, GEMM_SMEM);
    cudaFuncSetAttribute(scores_h,  cudaFuncAttributeMaxDynamicSharedMemorySize, SCORES_SMEM);
    cudaFuncSetAttribute(av_h,      cudaFuncAttributeMaxDynamicSharedMemorySize, AV_SMEM);

    // 0) pack + convert weights (single pass) and biases
    cvt_all<<<12288, 256>>>(wq, wk, wv, wo, w1, w2, wH);
    cvt_bias<<<12, 256>>>(bq, bk, bv, bqkv);

    // 1) LN1 -> half
    ln_kernel<<<ROWS, 256>>>(input, ln1_g, ln1_b, xh);
    // 2) fused QKV projection (one GEMM, N=3072)
    gemm_h<0><<<dim3(QKV_STR/128, ROWS/128), 256, GEMM_SMEM>>>(
        xh, wqkvH, bqkv, nullptr, qkvh, ROWS, QKV_STR, EMB);
    // 3) attention
    scores_h<<<dim3(4, 4, BH), 256, SCORES_SMEM>>>(qkvh, scores);
    softmax_kernel<<<BH * SEQ, 128>>>(scores, phh);
    av_h<<<dim3(4, BH), 256, AV_SMEM>>>(phh, qkvh, ah);
    // 4) output projection + bias + residual (fp32 out)
    gemm_h<2><<<dim3(EMB/128, ROWS/128), 256, GEMM_SMEM>>>(
        ah, woH, bo, input, x, ROWS, EMB, EMB);
    // 5) LN2 -> half
    ln_kernel<<<ROWS, 256>>>(x, ln2_g, ln2_b, xh);
    // 6) MLP up + bias + GELU -> half
    gemm_h<1><<<dim3(FF/128, ROWS/128), 256, GEMM_SMEM>>>(
        xh, w1H, b1, nullptr, hh, ROWS, FF, EMB);
    // 7) MLP down + bias + residual -> out (fp32)
    gemm_h<2><<<dim3(EMB/128, ROWS/128), 256, GEMM_SMEM>>>(
        hh, w2H, b2, x, out, ROWS, EMB, FF);
}

// round 15
// speedup vs baseline: 1.3994x; 1.0806x over previous
#include <cuda_runtime.h>
#include <cuda_fp16.h>
#include <mma.h>
#include <math.h>
#include <cstdint>

using namespace nvcuda;

// Problem dims
#define BATCH 16
#define SEQ   512
#define EMB   1024
#define FF    4096
#define HEADS 16
#define HDIM  64
#define ROWS  (BATCH*SEQ)        // 8192
#define BH    (BATCH*HEADS)      // 256
#define QKV_STR 3072             // packed q|k|v row stride

// ---------------- scratch (device globals; no allocation allowed) ----------------
__device__ __half g_wH[12*1024*1024];          // wqkv (3M) | wo (1M) | w1 (4M) | w2 (4M)
__device__ float  g_bqkv[3072];                // packed bias
__device__ __half g_xh[ROWS*EMB];              // LN out (half)
__device__ __half g_qkvh[(size_t)ROWS*QKV_STR];// packed q|k|v (half)
__device__ __half g_ah[ROWS*EMB];              // attention out (half)
__device__ __half g_hh[ROWS*FF];               // MLP hidden (half)
__device__ float  g_scores[(size_t)BH*SEQ*SEQ];
__device__ __half g_ph[(size_t)BH*SEQ*SEQ];    // softmax probs (half)
__device__ float  g_x[ROWS*EMB];               // residual stream (fp32)

// ---------------- helpers ----------------
__device__ __forceinline__ void cp_async16(void* smem_dst, const void* gsrc) {
    unsigned s = (unsigned)__cvta_generic_to_shared(smem_dst);
    asm volatile("cp.async.cg.shared.global [%0], [%1], 16;\n" :: "r"(s), "l"(gsrc));
}
__device__ __forceinline__ void cp_commit() {
    asm volatile("cp.async.commit_group;\n");
}
__device__ __forceinline__ float gelu_exact(float y) {
    return 0.5f * y * (1.0f + erff(y * 0.70710678118654752f));
}
__device__ __forceinline__ void st_half4(__half* p, float4 v) {
    __half2* p2 = reinterpret_cast<__half2*>(p);
    p2[0] = __floats2half2_rn(v.x, v.y);
    p2[1] = __floats2half2_rn(v.z, v.w);
}

// ---------------- fused weight conversion / packing ----------------
__global__ void cvt_all(const float* __restrict__ wq, const float* __restrict__ wk,
                        const float* __restrict__ wv, const float* __restrict__ wo,
                        const float* __restrict__ w1, const float* __restrict__ w2,
                        __half* __restrict__ d) {
    size_t i = (size_t)blockIdx.x * blockDim.x + threadIdx.x;
    if (i < 786432) {
        int seg = (int)(i >> 18);              // 0,1,2
        size_t li = i & 262143;
        int r = (int)(li >> 8), c = (int)(li & 255);
        const float* src = seg == 0 ? wq : (seg == 1 ? wk : wv);
        float4 v = reinterpret_cast<const float4*>(src)[li];
        st_half4(d + ((size_t)r * 768 + seg * 256 + c) * 4, v);
    } else if (i < 1048576) {
        size_t li = i - 786432;
        float4 v = reinterpret_cast<const float4*>(wo)[li];
        st_half4(d + i * 4, v);
    } else if (i < 2097152) {
        size_t li = i - 1048576;
        float4 v = reinterpret_cast<const float4*>(w1)[li];
        st_half4(d + i * 4, v);
    } else {
        size_t li = i - 2097152;
        float4 v = reinterpret_cast<const float4*>(w2)[li];
        st_half4(d + i * 4, v);
    }
}

__global__ void cvt_bias(const float* __restrict__ bq, const float* __restrict__ bk,
                         const float* __restrict__ bv, float* __restrict__ dst) {
    int i = blockIdx.x * blockDim.x + threadIdx.x;   // 0..3071
    const float* s = i < 1024 ? bq : (i < 2048 ? bk : bv);
    dst[i] = s[i & 1023];
}

// ---------------- LayerNorm: fp32 in, half out ----------------
__global__ void ln_kernel(const float* __restrict__ in, const float* __restrict__ gam,
                          const float* __restrict__ bet, __half* __restrict__ out) {
    int row = blockIdx.x;
    int t = threadIdx.x;
    const float4* inr = reinterpret_cast<const float4*>(in + (size_t)row * EMB);
    float4 x = inr[t];
    float s  = x.x + x.y + x.z + x.w;
    float sq = x.x*x.x + x.y*x.y + x.z*x.z + x.w*x.w;
    #pragma unroll
    for (int o = 16; o > 0; o >>= 1) {
        s  += __shfl_xor_sync(0xffffffffu, s,  o);
        sq += __shfl_xor_sync(0xffffffffu, sq, o);
    }
    __shared__ float sa[8], sb[8];
    int w = t >> 5, l = t & 31;
    if (l == 0) { sa[w] = s; sb[w] = sq; }
    __syncthreads();
    s = 0.f; sq = 0.f;
    #pragma unroll
    for (int i = 0; i < 8; i++) { s += sa[i]; sq += sb[i]; }
    float mean = s * (1.0f / EMB);
    float var  = sq * (1.0f / EMB) - mean * mean;
    float rstd = rsqrtf(var + 1e-5f);
    float4 g4 = reinterpret_cast<const float4*>(gam)[t];
    float4 b4 = reinterpret_cast<const float4*>(bet)[t];
    float4 o4;
    o4.x = (x.x - mean) * rstd * g4.x + b4.x;
    o4.y = (x.y - mean) * rstd * g4.y + b4.y;
    o4.z = (x.z - mean) * rstd * g4.z + b4.z;
    o4.w = (x.w - mean) * rstd * g4.w + b4.w;
    st_half4(out + (size_t)row * EMB + t * 4, o4);
}

// ---------------- FP16 GEMM: 128x128 block, warp 64x32, BK=64, 3-stage pipeline ----
// Hoisted address math; single barrier per K-chunk.
// EPI: 0 = +bias -> half    1 = +bias,GELU -> half    2 = +bias,+res -> float
#define ALD 72     // halves per A row
#define BLD 136    // halves per B row
#define ASTG_H (128*ALD)
#define BSTG_H (64*BLD)
#define STG_BYTES ((ASTG_H + BSTG_H)*2)  // 35840
#define GEMM_SMEM (3*STG_BYTES)          // 107520

template<int EPI>
__global__ __launch_bounds__(256, 2)
void gemm_h(const __half* __restrict__ A, const __half* __restrict__ B,
            const float* __restrict__ bias, const float* __restrict__ res,
            void* __restrict__ Cout, int M, int N, int K) {
    extern __shared__ char smraw[];
    float* Cs = (float*)smraw;   // epilogue alias [128][132]

    const int m0 = blockIdx.y * 128;
    const int n0 = blockIdx.x * 128;
    const int tid = threadIdx.x;
    const int warp = tid >> 5;
    const int wm = warp >> 2;      // 0..1
    const int wn = warp & 3;       // 0..3

    wmma::fragment<wmma::accumulator, 16, 16, 16, float> acc[4][2];
    #pragma unroll
    for (int i = 0; i < 4; i++)
        #pragma unroll
        for (int j = 0; j < 2; j++)
            wmma::fill_fragment(acc[i][j], 0.0f);

    // hoisted per-thread addresses
    const int arow = tid >> 3;              // 0..31
    const int acol = (tid & 7) << 3;        // 0..56
    const int brow = tid >> 4;              // 0..15
    const int bcol = (tid & 15) << 3;       // 0..120
    const __half* aPre = A + (size_t)(m0 + arow) * K + acol;   // next prefetch chunk
    const __half* bPre = B + (size_t)brow * N + n0 + bcol;
    const size_t aStride32 = (size_t)32 * K;
    const size_t bStride16 = (size_t)16 * N;
    const uint32_t saOff = arow * ALD + acol;
    const uint32_t sbOff = brow * BLD + bcol;

    auto load_stage = [&](int st) {
        __half* as = (__half*)(smraw + st * STG_BYTES);
        __half* bs = as + ASTG_H;
        #pragma unroll
        for (int p = 0; p < 4; p++)
            cp_async16(as + saOff + p * (32 * ALD), aPre + p * aStride32);
        #pragma unroll
        for (int p = 0; p < 4; p++)
            cp_async16(bs + sbOff + p * (16 * BLD), bPre + p * bStride16);
        cp_commit();
        aPre += 64;               // advance one K-chunk
        bPre += (size_t)64 * N;
    };

    const int NT = K >> 6;
    load_stage(0);
    load_stage(1);

    int st = 0;
    for (int kt = 0; kt < NT; kt++) {
        if (kt < NT - 1) asm volatile("cp.async.wait_group 1;\n");
        else             asm volatile("cp.async.wait_group 0;\n");
        __syncthreads();
        // prefetch chunk kt+2 into stage (st+2)%3 — last read at kt-1, safe after barrier
        if (kt + 2 < NT) {
            int st2 = st + 2; if (st2 >= 3) st2 -= 3;
            load_stage(st2);
        }
        const __half* as = (const __half*)(smraw + st * STG_BYTES);
        const __half* bs = as + ASTG_H;
        #pragma unroll
        for (int ks = 0; ks < 4; ks++) {
            wmma::fragment<wmma::matrix_a, 16, 16, 16, __half, wmma::row_major> af[4];
            wmma::fragment<wmma::matrix_b, 16, 16, 16, __half, wmma::row_major> bf[2];
            #pragma unroll
            for (int i = 0; i < 4; i++)
                wmma::load_matrix_sync(af[i], as + (wm * 64 + i * 16) * ALD + ks * 16, ALD);
            #pragma unroll
            for (int j = 0; j < 2; j++)
                wmma::load_matrix_sync(bf[j], bs + (ks * 16) * BLD + wn * 32 + j * 16, BLD);
            #pragma unroll
            for (int i = 0; i < 4; i++)
                #pragma unroll
                for (int j = 0; j < 2; j++)
                    wmma::mma_sync(acc[i][j], af[i], bf[j], acc[i][j]);
        }
        if (++st == 3) st = 0;
    }
    __syncthreads();   // all MMA reads done before Cs alias writes

    // epilogue via smem
    #pragma unroll
    for (int i = 0; i < 4; i++)
        #pragma unroll
        for (int j = 0; j < 2; j++)
            wmma::store_matrix_sync(Cs + (wm * 64 + i * 16) * 132 + wn * 32 + j * 16,
                                    acc[i][j], 132, wmma::mem_row_major);
    __syncthreads();

    #pragma unroll
    for (int p = 0; p < 16; p++) {
        int idx = tid + p * 256;              // 128 rows x 32 float4
        int r = idx >> 5, c = (idx & 31) << 2;
        float4 v = *reinterpret_cast<const float4*>(Cs + r * 132 + c);
        float4 b = *reinterpret_cast<const float4*>(bias + n0 + c);
        v.x += b.x; v.y += b.y; v.z += b.z; v.w += b.w;
        if (EPI == 1) {
            v.x = gelu_exact(v.x); v.y = gelu_exact(v.y);
            v.z = gelu_exact(v.z); v.w = gelu_exact(v.w);
        }
        if (EPI == 2) {
            float4 rr = *reinterpret_cast<const float4*>(res + (size_t)(m0 + r) * N + n0 + c);
            v.x += rr.x; v.y += rr.y; v.z += rr.z; v.w += rr.w;
            *reinterpret_cast<float4*>((float*)Cout + (size_t)(m0 + r) * N + n0 + c) = v;
        } else {
            st_half4((__half*)Cout + (size_t)(m0 + r) * N + n0 + c, v);
        }
    }
}

// ---------------- attention scores = (Q K^T) * 1/8, fp16 wmma, cp.async loads ------
#define QLD 72
#define SCORES_SMEM (2*128*QLD*2)   // 36864

__global__ __launch_bounds__(256, 2)
void scores_h(const __half* __restrict__ qkv, float* __restrict__ s) {
    extern __shared__ char smraw[];
    __half* Qs = (__half*)smraw;              // [128][QLD]
    __half* Ks = (__half*)smraw + 128*QLD;    // [128][QLD]
    int bh = blockIdx.z;
    int b = bh >> 4, h = bh & 15;
    int q0 = blockIdx.y * 128, k0 = blockIdx.x * 128;
    int tid = threadIdx.x;
    const __half* qbase = qkv + (size_t)(b * SEQ + q0) * QKV_STR + h * HDIM;
    const __half* kbase = qkv + (size_t)(b * SEQ + k0) * QKV_STR + 1024 + h * HDIM;
    #pragma unroll
    for (int p = 0; p < 4; p++) {
        int idx = tid + p * 256;              // 128 rows x 8 chunks (8 halves)
        int r = idx >> 3, c = (idx & 7) << 3;
        cp_async16(Qs + r * QLD + c, qbase + (size_t)r * QKV_STR + c);
        cp_async16(Ks + r * QLD + c, kbase + (size_t)r * QKV_STR + c);
    }
    cp_commit();
    asm volatile("cp.async.wait_group 0;\n");
    __syncthreads();

    int warp = tid >> 5, wm = warp >> 2, wn = warp & 3;
    wmma::fragment<wmma::accumulator, 16, 16, 16, float> acc[4][2];
    #pragma unroll
    for (int i = 0; i < 4; i++)
        #pragma unroll
        for (int j = 0; j < 2; j++)
            wmma::fill_fragment(acc[i][j], 0.0f);

    #pragma unroll
    for (int ks = 0; ks < 4; ks++) {
        wmma::fragment<wmma::matrix_a, 16, 16, 16, __half, wmma::row_major> af[4];
        wmma::fragment<wmma::matrix_b, 16, 16, 16, __half, wmma::col_major> bf[2];
        #pragma unroll
        for (int i = 0; i < 4; i++)
            wmma::load_matrix_sync(af[i], Qs + (wm * 64 + i * 16) * QLD + ks * 16, QLD);
        #pragma unroll
        for (int j = 0; j < 2; j++)
            wmma::load_matrix_sync(bf[j], Ks + (wn * 32 + j * 16) * QLD + ks * 16, QLD);
        #pragma unroll
        for (int i = 0; i < 4; i++)
            #pragma unroll
            for (int j = 0; j < 2; j++)
                wmma::mma_sync(acc[i][j], af[i], bf[j], acc[i][j]);
    }

    #pragma unroll
    for (int i = 0; i < 4; i++)
        #pragma unroll
        for (int j = 0; j < 2; j++) {
            #pragma unroll
            for (int e = 0; e < acc[i][j].num_elements; e++)
                acc[i][j].x[e] *= 0.125f;
            wmma::store_matrix_sync(
                s + ((size_t)bh * SEQ + q0 + wm * 64 + i * 16) * SEQ + k0 + wn * 32 + j * 16,
                acc[i][j], SEQ, wmma::mem_row_major);
        }
}

// ---------------- softmax: warp-per-row (8 rows / 256-thr block) ----------------
__global__ void softmax_kernel(const float* __restrict__ s, __half* __restrict__ ph) {
    size_t row = (size_t)blockIdx.x * 8 + (threadIdx.x >> 5);
    int l = threadIdx.x & 31;
    const float4* p = reinterpret_cast<const float4*>(s + row * SEQ);
    float4 x[4];
    float m = -1e30f;
    #pragma unroll
    for (int j = 0; j < 4; j++) {
        x[j] = p[l + 32 * j];
        m = fmaxf(m, fmaxf(fmaxf(x[j].x, x[j].y), fmaxf(x[j].z, x[j].w)));
    }
    #pragma unroll
    for (int o = 16; o > 0; o >>= 1) m = fmaxf(m, __shfl_xor_sync(0xffffffffu, m, o));
    float sum = 0.f;
    #pragma unroll
    for (int j = 0; j < 4; j++) {
        x[j].x = __expf(x[j].x - m); x[j].y = __expf(x[j].y - m);
        x[j].z = __expf(x[j].z - m); x[j].w = __expf(x[j].w - m);
        sum += x[j].x + x[j].y + x[j].z + x[j].w;
    }
    #pragma unroll
    for (int o = 16; o > 0; o >>= 1) sum += __shfl_xor_sync(0xffffffffu, sum, o);
    float inv = 1.0f / sum;
    #pragma unroll
    for (int j = 0; j < 4; j++) {
        float4 v; v.x = x[j].x*inv; v.y = x[j].y*inv; v.z = x[j].z*inv; v.w = x[j].w*inv;
        st_half4(ph + row * SEQ + (l + 32 * j) * 4, v);
    }
}

// ---------------- AV: attn = P V, fp16 wmma, 3-stage cp.async pipeline ----------------
#define AV_STG ((128*QLD + 64*QLD)*2)    // 27648 bytes per stage
#define AV_SMEM (3*AV_STG)               // 82944

__global__ __launch_bounds__(256, 2)
void av_h(const __half* __restrict__ ph, const __half* __restrict__ qkv,
          __half* __restrict__ o) {
    extern __shared__ char smraw[];
    float* Cs = (float*)smraw;                // epilogue alias [128][68] (34816 B)
    int bh = blockIdx.y;
    int b = bh >> 4, h = bh & 15;
    int q0 = blockIdx.x * 128;
    int tid = threadIdx.x;
    int warp = tid >> 5, wm = warp >> 1, wn = warp & 1;
    const __half* pbase = ph + ((size_t)bh * SEQ + q0) * SEQ;
    const __half* vbase = qkv + (size_t)b * SEQ * QKV_STR + 2048 + h * HDIM;

    const int prow = tid >> 1;                // unused helper removed; use idx math below
    (void)prow;

    wmma::fragment<wmma::accumulator, 16, 16, 16, float> acc[2][2];
    #pragma unroll
    for (int i = 0; i < 2; i++)
        #pragma unroll
        for (int j = 0; j < 2; j++)
            wmma::fill_fragment(acc[i][j], 0.0f);

    auto load_pv = [&](int st, int kc) {
        __half* Ps = (__half*)(smraw + st * AV_STG);
        __half* Vs = Ps + 128 * QLD;
        #pragma unroll
        for (int p = 0; p < 4; p++) {          // P: 128 rows x 8 chunks
            int idx = tid + p * 256;
            int r = idx >> 3, c = (idx & 7) << 3;
            cp_async16(Ps + r * QLD + c, pbase + (size_t)r * SEQ + kc + c);
        }
        #pragma unroll
        for (int p = 0; p < 2; p++) {          // V: 64 rows x 8 chunks
            int idx = tid + p * 256;
            int r = idx >> 3, c = (idx & 7) << 3;
            cp_async16(Vs + r * QLD + c, vbase + (size_t)(kc + r) * QKV_STR + c);
        }
        cp_commit();
    };

    load_pv(0, 0);
    load_pv(1, 64);

    int st = 0;
    for (int i8 = 0; i8 < 8; i8++) {
        if (i8 < 7) asm volatile("cp.async.wait_group 1;\n");
        else        asm volatile("cp.async.wait_group 0;\n");
        __syncthreads();
        if (i8 + 2 < 8) {
            int st2 = st + 2; if (st2 >= 3) st2 -= 3;
            load_pv(st2, (i8 + 2) * 64);
        }
        const __half* Ps = (const __half*)(smraw + st * AV_STG);
        const __half* Vs = Ps + 128 * QLD;
        #pragma unroll
        for (int ks = 0; ks < 4; ks++) {
            wmma::fragment<wmma::matrix_a, 16, 16, 16, __half, wmma::row_major> af[2];
            wmma::fragment<wmma::matrix_b, 16, 16, 16, __half, wmma::row_major> bf[2];
            #pragma unroll
            for (int i = 0; i < 2; i++)
                wmma::load_matrix_sync(af[i], Ps + (wm * 32 + i * 16) * QLD + ks * 16, QLD);
            #pragma unroll
            for (int j = 0; j < 2; j++)
                wmma::load_matrix_sync(bf[j], Vs + (ks * 16) * QLD + wn * 32 + j * 16, QLD);
            #pragma unroll
            for (int i = 0; i < 2; i++)
                #pragma unroll
                for (int j = 0; j < 2; j++)
                    wmma::mma_sync(acc[i][j], af[i], bf[j], acc[i][j]);
        }
        if (++st == 3) st = 0;
    }
    __syncthreads();

    #pragma unroll
    for (int i = 0; i < 2; i++)
        #pragma unroll
        for (int j = 0; j < 2; j++)
            wmma::store_matrix_sync(Cs + (wm * 32 + i * 16) * 68 + wn * 32 + j * 16,
                                    acc[i][j], 68, wmma::mem_row_major);
    __syncthreads();
    #pragma unroll
    for (int p = 0; p < 8; p++) {
        int idx = tid + p * 256;              // 128 rows x 16 float4
        int r = idx >> 4, c = (idx & 15) << 2;
        float4 vv = *reinterpret_cast<const float4*>(Cs + r * 68 + c);
        st_half4(o + (size_t)(b * SEQ + q0 + r) * EMB + h * HDIM + c, vv);
    }
}

// ---------------- driver ----------------
extern "C" void kernel_launch(void* const* d_in, const int* in_sizes, int n_in,
                              void* d_out, int out_size) {
    const float* input = (const float*)d_in[0];
    const float* ln1_g = (const float*)d_in[1];
    const float* ln1_b = (const float*)d_in[2];
    const float* wq    = (const float*)d_in[3];
    const float* bq    = (const float*)d_in[4];
    const float* wk    = (const float*)d_in[5];
    const float* bk    = (const float*)d_in[6];
    const float* wv    = (const float*)d_in[7];
    const float* bv    = (const float*)d_in[8];
    const float* wo    = (const float*)d_in[9];
    const float* bo    = (const float*)d_in[10];
    const float* ln2_g = (const float*)d_in[11];
    const float* ln2_b = (const float*)d_in[12];
    const float* w1    = (const float*)d_in[13];
    const float* b1    = (const float*)d_in[14];
    const float* w2    = (const float*)d_in[15];
    const float* b2    = (const float*)d_in[16];
    float* out = (float*)d_out;

    __half *wH, *xh, *qkvh, *ah, *hh, *phh;
    float *scores, *x, *bqkv;
    cudaGetSymbolAddress((void**)&wH,     g_wH);
    cudaGetSymbolAddress((void**)&bqkv,   g_bqkv);
    cudaGetSymbolAddress((void**)&xh,     g_xh);
    cudaGetSymbolAddress((void**)&qkvh,   g_qkvh);
    cudaGetSymbolAddress((void**)&ah,     g_ah);
    cudaGetSymbolAddress((void**)&hh,     g_hh);
    cudaGetSymbolAddress((void**)&phh,    g_ph);
    cudaGetSymbolAddress((void**)&scores, g_scores);
    cudaGetSymbolAddress((void**)&x,      g_x);

    __half* wqkvH = wH;                     // [1024,3072]
    __half* woH   = wH + 3145728;           // [1024,1024]
    __half* w1H   = wH + 4194304;           // [1024,4096]
    __half* w2H   = wH + 8388608;           // [4096,1024]

    cudaFuncSetAttribute(gemm_h<0>, cudaFuncAttributeMaxDynamicSharedMemorySize, GEMM_SMEM);
    cudaFuncSetAttribute(gemm_h<1>, cudaFuncAttributeMaxDynamicSharedMemorySize, GEMM_SMEM);
    cudaFuncSetAttribute(gemm_h<2>, cudaFuncAttributeMaxDynamicSharedMemorySize, GEMM_SMEM);
    cudaFuncSetAttribute(scores_h,  cudaFuncAttributeMaxDynamicSharedMemorySize, SCORES_SMEM);
    cudaFuncSetAttribute(av_h,      cudaFuncAttributeMaxDynamicSharedMemorySize, AV_SMEM);

    // 0) pack + convert weights (single pass) and biases
    cvt_all<<<12288, 256>>>(wq, wk, wv, wo, w1, w2, wH);
    cvt_bias<<<12, 256>>>(bq, bk, bv, bqkv);

    // 1) LN1 -> half
    ln_kernel<<<ROWS, 256>>>(input, ln1_g, ln1_b, xh);
    // 2) fused QKV projection (one GEMM, N=3072)
    gemm_h<0><<<dim3(QKV_STR/128, ROWS/128), 256, GEMM_SMEM>>>(
        xh, wqkvH, bqkv, nullptr, qkvh, ROWS, QKV_STR, EMB);
    // 3) attention
    scores_h<<<dim3(4, 4, BH), 256, SCORES_SMEM>>>(qkvh, scores);
    softmax_kernel<<<BH * SEQ / 8, 256>>>(scores, phh);
    av_h<<<dim3(4, BH), 256, AV_SMEM>>>(phh, qkvh, ah);
    // 4) output projection + bias + residual (fp32 out)
    gemm_h<2><<<dim3(EMB/128, ROWS/128), 256, GEMM_SMEM>>>(
        ah, woH, bo, input, x, ROWS, EMB, EMB);
    // 5) LN2 -> half
    ln_kernel<<<ROWS, 256>>>(x, ln2_g, ln2_b, xh);
    // 6) MLP up + bias + GELU -> half
    gemm_h<1><<<dim3(FF/128, ROWS/128), 256, GEMM_SMEM>>>(
        xh, w1H, b1, nullptr, hh, ROWS, FF, EMB);
    // 7) MLP down + bias + residual -> out (fp32)
    gemm_h<2><<<dim3(EMB/128, ROWS/128), 256, GEMM_SMEM>>>(
        hh, w2H, b2, x, out, ROWS, EMB, FF);
}

// round 17
// speedup vs baseline: 1.4281x; 1.0205x over previous
#include <cuda_runtime.h>
#include <cuda_fp16.h>
#include <mma.h>
#include <math.h>
#include <cstdint>

using namespace nvcuda;

// Problem dims
#define BATCH 16
#define SEQ   512
#define EMB   1024
#define FF    4096
#define HEADS 16
#define HDIM  64
#define ROWS  (BATCH*SEQ)        // 8192
#define BH    (BATCH*HEADS)      // 256
#define QKV_STR 3072             // packed q|k|v row stride

// ---------------- scratch (device globals; no allocation allowed) ----------------
__device__ __half g_wH[12*1024*1024];          // wqkv (3M) | wo (1M) | w1 (4M) | w2 (4M)
__device__ float  g_bqkv[3072];                // packed bias
__device__ __half g_xh[ROWS*EMB];              // LN out (half)
__device__ __half g_qkvh[(size_t)ROWS*QKV_STR];// packed q|k|v (half)
__device__ __half g_ah[ROWS*EMB];              // attention out (half)
__device__ __half g_hh[ROWS*FF];               // MLP hidden (half)
__device__ __half g_scores[(size_t)BH*SEQ*SEQ];// scores (half, pre-scaled)
__device__ __half g_ph[(size_t)BH*SEQ*SEQ];    // softmax probs (half)
__device__ float  g_x[ROWS*EMB];               // residual stream (fp32)

// ---------------- helpers ----------------
__device__ __forceinline__ void cp_async16(void* smem_dst, const void* gsrc) {
    unsigned s = (unsigned)__cvta_generic_to_shared(smem_dst);
    asm volatile("cp.async.cg.shared.global [%0], [%1], 16;\n" :: "r"(s), "l"(gsrc));
}
__device__ __forceinline__ void cp_commit() {
    asm volatile("cp.async.commit_group;\n");
}
__device__ __forceinline__ float gelu_exact(float y) {
    return 0.5f * y * (1.0f + erff(y * 0.70710678118654752f));
}
__device__ __forceinline__ void st_half4(__half* p, float4 v) {
    __half2* p2 = reinterpret_cast<__half2*>(p);
    p2[0] = __floats2half2_rn(v.x, v.y);
    p2[1] = __floats2half2_rn(v.z, v.w);
}

// ---------------- fused weight conversion / packing ----------------
__global__ void cvt_all(const float* __restrict__ wq, const float* __restrict__ wk,
                        const float* __restrict__ wv, const float* __restrict__ wo,
                        const float* __restrict__ w1, const float* __restrict__ w2,
                        __half* __restrict__ d) {
    size_t i = (size_t)blockIdx.x * blockDim.x + threadIdx.x;
    if (i < 786432) {
        int seg = (int)(i >> 18);              // 0,1,2
        size_t li = i & 262143;
        int r = (int)(li >> 8), c = (int)(li & 255);
        const float* src = seg == 0 ? wq : (seg == 1 ? wk : wv);
        float4 v = reinterpret_cast<const float4*>(src)[li];
        st_half4(d + ((size_t)r * 768 + seg * 256 + c) * 4, v);
    } else if (i < 1048576) {
        size_t li = i - 786432;
        float4 v = reinterpret_cast<const float4*>(wo)[li];
        st_half4(d + i * 4, v);
    } else if (i < 2097152) {
        size_t li = i - 1048576;
        float4 v = reinterpret_cast<const float4*>(w1)[li];
        st_half4(d + i * 4, v);
    } else {
        size_t li = i - 2097152;
        float4 v = reinterpret_cast<const float4*>(w2)[li];
        st_half4(d + i * 4, v);
    }
}

__global__ void cvt_bias(const float* __restrict__ bq, const float* __restrict__ bk,
                         const float* __restrict__ bv, float* __restrict__ dst) {
    int i = blockIdx.x * blockDim.x + threadIdx.x;   // 0..3071
    const float* s = i < 1024 ? bq : (i < 2048 ? bk : bv);
    dst[i] = s[i & 1023];
}

// ---------------- LayerNorm: fp32 in, half out ----------------
__global__ void ln_kernel(const float* __restrict__ in, const float* __restrict__ gam,
                          const float* __restrict__ bet, __half* __restrict__ out) {
    int row = blockIdx.x;
    int t = threadIdx.x;
    const float4* inr = reinterpret_cast<const float4*>(in + (size_t)row * EMB);
    float4 x = inr[t];
    float s  = x.x + x.y + x.z + x.w;
    float sq = x.x*x.x + x.y*x.y + x.z*x.z + x.w*x.w;
    #pragma unroll
    for (int o = 16; o > 0; o >>= 1) {
        s  += __shfl_xor_sync(0xffffffffu, s,  o);
        sq += __shfl_xor_sync(0xffffffffu, sq, o);
    }
    __shared__ float sa[8], sb[8];
    int w = t >> 5, l = t & 31;
    if (l == 0) { sa[w] = s; sb[w] = sq; }
    __syncthreads();
    s = 0.f; sq = 0.f;
    #pragma unroll
    for (int i = 0; i < 8; i++) { s += sa[i]; sq += sb[i]; }
    float mean = s * (1.0f / EMB);
    float var  = sq * (1.0f / EMB) - mean * mean;
    float rstd = rsqrtf(var + 1e-5f);
    float4 g4 = reinterpret_cast<const float4*>(gam)[t];
    float4 b4 = reinterpret_cast<const float4*>(bet)[t];
    float4 o4;
    o4.x = (x.x - mean) * rstd * g4.x + b4.x;
    o4.y = (x.y - mean) * rstd * g4.y + b4.y;
    o4.z = (x.z - mean) * rstd * g4.z + b4.z;
    o4.w = (x.w - mean) * rstd * g4.w + b4.w;
    st_half4(out + (size_t)row * EMB + t * 4, o4);
}

// ---------------- FP16 GEMM: 128x128 block, warp 64x32, BK=64, 3-stage pipeline ----
// EPI: 0 = +bias -> half    1 = +bias,GELU -> half    2 = +bias,+res -> float
#define ALD 72     // halves per A row
#define BLD 136    // halves per B row
#define ASTG_H (128*ALD)
#define BSTG_H (64*BLD)
#define STG_BYTES ((ASTG_H + BSTG_H)*2)  // 35840
#define GEMM_SMEM (3*STG_BYTES)          // 107520

template<int EPI>
__global__ __launch_bounds__(256, 2)
void gemm_h(const __half* __restrict__ A, const __half* __restrict__ B,
            const float* __restrict__ bias, const float* __restrict__ res,
            void* __restrict__ Cout, int M, int N, int K) {
    extern __shared__ char smraw[];
    float* Cs = (float*)smraw;   // epilogue alias [128][132]

    const int m0 = blockIdx.y * 128;
    const int n0 = blockIdx.x * 128;
    const int tid = threadIdx.x;
    const int warp = tid >> 5;
    const int wm = warp >> 2;      // 0..1
    const int wn = warp & 3;       // 0..3

    wmma::fragment<wmma::accumulator, 16, 16, 16, float> acc[4][2];
    #pragma unroll
    for (int i = 0; i < 4; i++)
        #pragma unroll
        for (int j = 0; j < 2; j++)
            wmma::fill_fragment(acc[i][j], 0.0f);

    // hoisted per-thread addresses
    const int arow = tid >> 3;              // 0..31
    const int acol = (tid & 7) << 3;        // 0..56
    const int brow = tid >> 4;              // 0..15
    const int bcol = (tid & 15) << 3;       // 0..120
    const __half* aPre = A + (size_t)(m0 + arow) * K + acol;
    const __half* bPre = B + (size_t)brow * N + n0 + bcol;
    const size_t aStride32 = (size_t)32 * K;
    const size_t bStride16 = (size_t)16 * N;
    const uint32_t saOff = arow * ALD + acol;
    const uint32_t sbOff = brow * BLD + bcol;

    auto load_stage = [&](int st) {
        __half* as = (__half*)(smraw + st * STG_BYTES);
        __half* bs = as + ASTG_H;
        #pragma unroll
        for (int p = 0; p < 4; p++)
            cp_async16(as + saOff + p * (32 * ALD), aPre + p * aStride32);
        #pragma unroll
        for (int p = 0; p < 4; p++)
            cp_async16(bs + sbOff + p * (16 * BLD), bPre + p * bStride16);
        cp_commit();
        aPre += 64;
        bPre += (size_t)64 * N;
    };

    const int NT = K >> 6;
    load_stage(0);
    load_stage(1);

    int st = 0;
    for (int kt = 0; kt < NT; kt++) {
        if (kt < NT - 1) asm volatile("cp.async.wait_group 1;\n");
        else             asm volatile("cp.async.wait_group 0;\n");
        __syncthreads();
        if (kt + 2 < NT) {
            int st2 = st + 2; if (st2 >= 3) st2 -= 3;
            load_stage(st2);
        }
        const __half* as = (const __half*)(smraw + st * STG_BYTES);
        const __half* bs = as + ASTG_H;
        #pragma unroll
        for (int ks = 0; ks < 4; ks++) {
            wmma::fragment<wmma::matrix_a, 16, 16, 16, __half, wmma::row_major> af[4];
            wmma::fragment<wmma::matrix_b, 16, 16, 16, __half, wmma::row_major> bf[2];
            #pragma unroll
            for (int i = 0; i < 4; i++)
                wmma::load_matrix_sync(af[i], as + (wm * 64 + i * 16) * ALD + ks * 16, ALD);
            #pragma unroll
            for (int j = 0; j < 2; j++)
                wmma::load_matrix_sync(bf[j], bs + (ks * 16) * BLD + wn * 32 + j * 16, BLD);
            #pragma unroll
            for (int i = 0; i < 4; i++)
                #pragma unroll
                for (int j = 0; j < 2; j++)
                    wmma::mma_sync(acc[i][j], af[i], bf[j], acc[i][j]);
        }
        if (++st == 3) st = 0;
    }
    __syncthreads();

    // epilogue via smem
    #pragma unroll
    for (int i = 0; i < 4; i++)
        #pragma unroll
        for (int j = 0; j < 2; j++)
            wmma::store_matrix_sync(Cs + (wm * 64 + i * 16) * 132 + wn * 32 + j * 16,
                                    acc[i][j], 132, wmma::mem_row_major);
    __syncthreads();

    #pragma unroll
    for (int p = 0; p < 16; p++) {
        int idx = tid + p * 256;              // 128 rows x 32 float4
        int r = idx >> 5, c = (idx & 31) << 2;
        float4 v = *reinterpret_cast<const float4*>(Cs + r * 132 + c);
        float4 b = *reinterpret_cast<const float4*>(bias + n0 + c);
        v.x += b.x; v.y += b.y; v.z += b.z; v.w += b.w;
        if (EPI == 1) {
            v.x = gelu_exact(v.x); v.y = gelu_exact(v.y);
            v.z = gelu_exact(v.z); v.w = gelu_exact(v.w);
        }
        if (EPI == 2) {
            float4 rr = *reinterpret_cast<const float4*>(res + (size_t)(m0 + r) * N + n0 + c);
            v.x += rr.x; v.y += rr.y; v.z += rr.z; v.w += rr.w;
            *reinterpret_cast<float4*>((float*)Cout + (size_t)(m0 + r) * N + n0 + c) = v;
        } else {
            st_half4((__half*)Cout + (size_t)(m0 + r) * N + n0 + c, v);
        }
    }
}

// ---------------- attention scores = (Q K^T) * 1/8 -> HALF, fp16 wmma --------------
#define QLD 72
#define SCORES_SMEM 67584   // max(Q/K tiles 36864, epilogue Cs 128*132*4 = 67584)

__global__ __launch_bounds__(256, 2)
void scores_h(const __half* __restrict__ qkv, __half* __restrict__ s) {
    extern __shared__ char smraw[];
    __half* Qs = (__half*)smraw;              // [128][QLD]
    __half* Ks = (__half*)smraw + 128*QLD;    // [128][QLD]
    float* Cs = (float*)smraw;                // epilogue alias [128][132]
    int bh = blockIdx.z;
    int b = bh >> 4, h = bh & 15;
    int q0 = blockIdx.y * 128, k0 = blockIdx.x * 128;
    int tid = threadIdx.x;
    const __half* qbase = qkv + (size_t)(b * SEQ + q0) * QKV_STR + h * HDIM;
    const __half* kbase = qkv + (size_t)(b * SEQ + k0) * QKV_STR + 1024 + h * HDIM;
    #pragma unroll
    for (int p = 0; p < 4; p++) {
        int idx = tid + p * 256;              // 128 rows x 8 chunks (8 halves)
        int r = idx >> 3, c = (idx & 7) << 3;
        cp_async16(Qs + r * QLD + c, qbase + (size_t)r * QKV_STR + c);
        cp_async16(Ks + r * QLD + c, kbase + (size_t)r * QKV_STR + c);
    }
    cp_commit();
    asm volatile("cp.async.wait_group 0;\n");
    __syncthreads();

    int warp = tid >> 5, wm = warp >> 2, wn = warp & 3;
    wmma::fragment<wmma::accumulator, 16, 16, 16, float> acc[4][2];
    #pragma unroll
    for (int i = 0; i < 4; i++)
        #pragma unroll
        for (int j = 0; j < 2; j++)
            wmma::fill_fragment(acc[i][j], 0.0f);

    #pragma unroll
    for (int ks = 0; ks < 4; ks++) {
        wmma::fragment<wmma::matrix_a, 16, 16, 16, __half, wmma::row_major> af[4];
        wmma::fragment<wmma::matrix_b, 16, 16, 16, __half, wmma::col_major> bf[2];
        #pragma unroll
        for (int i = 0; i < 4; i++)
            wmma::load_matrix_sync(af[i], Qs + (wm * 64 + i * 16) * QLD + ks * 16, QLD);
        #pragma unroll
        for (int j = 0; j < 2; j++)
            wmma::load_matrix_sync(bf[j], Ks + (wn * 32 + j * 16) * QLD + ks * 16, QLD);
        #pragma unroll
        for (int i = 0; i < 4; i++)
            #pragma unroll
            for (int j = 0; j < 2; j++)
                wmma::mma_sync(acc[i][j], af[i], bf[j], acc[i][j]);
    }
    __syncthreads();   // Q/K reads complete before Cs alias writes

    #pragma unroll
    for (int i = 0; i < 4; i++)
        #pragma unroll
        for (int j = 0; j < 2; j++) {
            #pragma unroll
            for (int e = 0; e < acc[i][j].num_elements; e++)
                acc[i][j].x[e] *= 0.125f;
            wmma::store_matrix_sync(Cs + (wm * 64 + i * 16) * 132 + wn * 32 + j * 16,
                                    acc[i][j], 132, wmma::mem_row_major);
        }
    __syncthreads();

    #pragma unroll
    for (int p = 0; p < 16; p++) {
        int idx = tid + p * 256;              // 128 rows x 32 float4
        int r = idx >> 5, c = (idx & 31) << 2;
        float4 v = *reinterpret_cast<const float4*>(Cs + r * 132 + c);
        st_half4(s + ((size_t)bh * SEQ + q0 + r) * SEQ + k0 + c, v);
    }
}

// ---------------- softmax: half in, half out; warp-per-row (8 rows / block) -------
__global__ void softmax_kernel(const __half* __restrict__ s, __half* __restrict__ ph) {
    size_t row = (size_t)blockIdx.x * 8 + (threadIdx.x >> 5);
    int l = threadIdx.x & 31;
    const float4* p4 = reinterpret_cast<const float4*>(s + row * SEQ);   // 64 f4 of halves
    float4 raw[2];
    raw[0] = p4[l];
    raw[1] = p4[l + 32];
    float v[16];
    float m = -1e30f;
    #pragma unroll
    for (int j = 0; j < 2; j++) {
        const __half2* h2 = reinterpret_cast<const __half2*>(&raw[j]);
        #pragma unroll
        for (int t = 0; t < 4; t++) {
            float2 f = __half22float2(h2[t]);
            v[j * 8 + t * 2]     = f.x;
            v[j * 8 + t * 2 + 1] = f.y;
            m = fmaxf(m, fmaxf(f.x, f.y));
        }
    }
    #pragma unroll
    for (int o = 16; o > 0; o >>= 1) m = fmaxf(m, __shfl_xor_sync(0xffffffffu, m, o));
    float sum = 0.f;
    #pragma unroll
    for (int j = 0; j < 16; j++) { v[j] = __expf(v[j] - m); sum += v[j]; }
    #pragma unroll
    for (int o = 16; o > 0; o >>= 1) sum += __shfl_xor_sync(0xffffffffu, sum, o);
    float inv = 1.0f / sum;
    __half* dst = ph + row * SEQ;
    #pragma unroll
    for (int j = 0; j < 2; j++) {
        float4 o4a, o4b;
        o4a.x = v[j*8+0]*inv; o4a.y = v[j*8+1]*inv; o4a.z = v[j*8+2]*inv; o4a.w = v[j*8+3]*inv;
        o4b.x = v[j*8+4]*inv; o4b.y = v[j*8+5]*inv; o4b.z = v[j*8+6]*inv; o4b.w = v[j*8+7]*inv;
        int base = (l + 32 * j) * 8;
        st_half4(dst + base, o4a);
        st_half4(dst + base + 4, o4b);
    }
}

// ---------------- AV: attn = P V, fp16 wmma, 3-stage cp.async pipeline ----------------
#define AV_STG ((128*QLD + 64*QLD)*2)    // 27648 bytes per stage
#define AV_SMEM (3*AV_STG)               // 82944

__global__ __launch_bounds__(256, 2)
void av_h(const __half* __restrict__ ph, const __half* __restrict__ qkv,
          __half* __restrict__ o) {
    extern __shared__ char smraw[];
    float* Cs = (float*)smraw;                // epilogue alias [128][68]
    int bh = blockIdx.y;
    int b = bh >> 4, h = bh & 15;
    int q0 = blockIdx.x * 128;
    int tid = threadIdx.x;
    int warp = tid >> 5, wm = warp >> 1, wn = warp & 1;
    const __half* pbase = ph + ((size_t)bh * SEQ + q0) * SEQ;
    const __half* vbase = qkv + (size_t)b * SEQ * QKV_STR + 2048 + h * HDIM;

    wmma::fragment<wmma::accumulator, 16, 16, 16, float> acc[2][2];
    #pragma unroll
    for (int i = 0; i < 2; i++)
        #pragma unroll
        for (int j = 0; j < 2; j++)
            wmma::fill_fragment(acc[i][j], 0.0f);

    auto load_pv = [&](int st, int kc) {
        __half* Ps = (__half*)(smraw + st * AV_STG);
        __half* Vs = Ps + 128 * QLD;
        #pragma unroll
        for (int p = 0; p < 4; p++) {          // P: 128 rows x 8 chunks
            int idx = tid + p * 256;
            int r = idx >> 3, c = (idx & 7) << 3;
            cp_async16(Ps + r * QLD + c, pbase + (size_t)r * SEQ + kc + c);
        }
        #pragma unroll
        for (int p = 0; p < 2; p++) {          // V: 64 rows x 8 chunks
            int idx = tid + p * 256;
            int r = idx >> 3, c = (idx & 7) << 3;
            cp_async16(Vs + r * QLD + c, vbase + (size_t)(kc + r) * QKV_STR + c);
        }
        cp_commit();
    };

    load_pv(0, 0);
    load_pv(1, 64);

    int st = 0;
    for (int i8 = 0; i8 < 8; i8++) {
        if (i8 < 7) asm volatile("cp.async.wait_group 1;\n");
        else        asm volatile("cp.async.wait_group 0;\n");
        __syncthreads();
        if (i8 + 2 < 8) {
            int st2 = st + 2; if (st2 >= 3) st2 -= 3;
            load_pv(st2, (i8 + 2) * 64);
        }
        const __half* Ps = (const __half*)(smraw + st * AV_STG);
        const __half* Vs = Ps + 128 * QLD;
        #pragma unroll
        for (int ks = 0; ks < 4; ks++) {
            wmma::fragment<wmma::matrix_a, 16, 16, 16, __half, wmma::row_major> af[2];
            wmma::fragment<wmma::matrix_b, 16, 16, 16, __half, wmma::row_major> bf[2];
            #pragma unroll
            for (int i = 0; i < 2; i++)
                wmma::load_matrix_sync(af[i], Ps + (wm * 32 + i * 16) * QLD + ks * 16, QLD);
            #pragma unroll
            for (int j = 0; j < 2; j++)
                wmma::load_matrix_sync(bf[j], Vs + (ks * 16) * QLD + wn * 32 + j * 16, QLD);
            #pragma unroll
            for (int i = 0; i < 2; i++)
                #pragma unroll
                for (int j = 0; j < 2; j++)
                    wmma::mma_sync(acc[i][j], af[i], bf[j], acc[i][j]);
        }
        if (++st == 3) st = 0;
    }
    __syncthreads();

    #pragma unroll
    for (int i = 0; i < 2; i++)
        #pragma unroll
        for (int j = 0; j < 2; j++)
            wmma::store_matrix_sync(Cs + (wm * 32 + i * 16) * 68 + wn * 32 + j * 16,
                                    acc[i][j], 68, wmma::mem_row_major);
    __syncthreads();
    #pragma unroll
    for (int p = 0; p < 8; p++) {
        int idx = tid + p * 256;              // 128 rows x 16 float4
        int r = idx >> 4, c = (idx & 15) << 2;
        float4 vv = *reinterpret_cast<const float4*>(Cs + r * 68 + c);
        st_half4(o + (size_t)(b * SEQ + q0 + r) * EMB + h * HDIM + c, vv);
    }
}

// ---------------- driver ----------------
extern "C" void kernel_launch(void* const* d_in, const int* in_sizes, int n_in,
                              void* d_out, int out_size) {
    const float* input = (const float*)d_in[0];
    const float* ln1_g = (const float*)d_in[1];
    const float* ln1_b = (const float*)d_in[2];
    const float* wq    = (const float*)d_in[3];
    const float* bq    = (const float*)d_in[4];
    const float* wk    = (const float*)d_in[5];
    const float* bk    = (const float*)d_in[6];
    const float* wv    = (const float*)d_in[7];
    const float* bv    = (const float*)d_in[8];
    const float* wo    = (const float*)d_in[9];
    const float* bo    = (const float*)d_in[10];
    const float* ln2_g = (const float*)d_in[11];
    const float* ln2_b = (const float*)d_in[12];
    const float* w1    = (const float*)d_in[13];
    const float* b1    = (const float*)d_in[14];
    const float* w2    = (const float*)d_in[15];
    const float* b2    = (const float*)d_in[16];
    float* out = (float*)d_out;

    __half *wH, *xh, *qkvh, *ah, *hh, *phh, *scores;
    float *x, *bqkv;
    cudaGetSymbolAddress((void**)&wH,     g_wH);
    cudaGetSymbolAddress((void**)&bqkv,   g_bqkv);
    cudaGetSymbolAddress((void**)&xh,     g_xh);
    cudaGetSymbolAddress((void**)&qkvh,   g_qkvh);
    cudaGetSymbolAddress((void**)&ah,     g_ah);
    cudaGetSymbolAddress((void**)&hh,     g_hh);
    cudaGetSymbolAddress((void**)&phh,    g_ph);
    cudaGetSymbolAddress((void**)&scores, g_scores);
    cudaGetSymbolAddress((void**)&x,      g_x);

    __half* wqkvH = wH;                     // [1024,3072]
    __half* woH   = wH + 3145728;           // [1024,1024]
    __half* w1H   = wH + 4194304;           // [1024,4096]
    __half* w2H   = wH + 8388608;           // [4096,1024]

    cudaFuncSetAttribute(gemm_h<0>, cudaFuncAttributeMaxDynamicSharedMemorySize, GEMM_SMEM);
    cudaFuncSetAttribute(gemm_h<1>, cudaFuncAttributeMaxDynamicSharedMemorySize, GEMM_SMEM);
    cudaFuncSetAttribute(gemm_h<2>, cudaFuncAttributeMaxDynamicSharedMemorySize, GEMM_SMEM);
    cudaFuncSetAttribute(scores_h,  cudaFuncAttributeMaxDynamicSharedMemorySize, SCORES_SMEM);
    cudaFuncSetAttribute(av_h,      cudaFuncAttributeMaxDynamicSharedMemorySize, AV_SMEM);

    // 0) pack + convert weights (single pass) and biases
    cvt_all<<<12288, 256>>>(wq, wk, wv, wo, w1, w2, wH);
    cvt_bias<<<12, 256>>>(bq, bk, bv, bqkv);

    // 1) LN1 -> half
    ln_kernel<<<ROWS, 256>>>(input, ln1_g, ln1_b, xh);
    // 2) fused QKV projection (one GEMM, N=3072)
    gemm_h<0><<<dim3(QKV_STR/128, ROWS/128), 256, GEMM_SMEM>>>(
        xh, wqkvH, bqkv, nullptr, qkvh, ROWS, QKV_STR, EMB);
    // 3) attention (half scores)
    scores_h<<<dim3(4, 4, BH), 256, SCORES_SMEM>>>(qkvh, scores);
    softmax_kernel<<<BH * SEQ / 8, 256>>>(scores, phh);
    av_h<<<dim3(4, BH), 256, AV_SMEM>>>(phh, qkvh, ah);
    // 4) output projection + bias + residual (fp32 out)
    gemm_h<2><<<dim3(EMB/128, ROWS/128), 256, GEMM_SMEM>>>(
        ah, woH, bo, input, x, ROWS, EMB, EMB);
    // 5) LN2 -> half
    ln_kernel<<<ROWS, 256>>>(x, ln2_g, ln2_b, xh);
    // 6) MLP up + bias + GELU -> half
    gemm_h<1><<<dim3(FF/128, ROWS/128), 256, GEMM_SMEM>>>(
        xh, w1H, b1, nullptr, hh, ROWS, FF, EMB);
    // 7) MLP down + bias + residual -> out (fp32)
    gemm_h<2><<<dim3(EMB/128, ROWS/128), 256, GEMM_SMEM>>>(
        hh, w2H, b2, x, out, ROWS, EMB, FF);
}